// round 1
// baseline (speedup 1.0000x reference)
#include <cuda_runtime.h>
#include <math.h>

#define K_DIM 256
#define HD 128
#define MAX_N 100000
#define MAX_E 1600000

// ---------------- scratch (static device arrays; no allocation) ----------------
__device__ float g_xw[(size_t)MAX_N * HD];   // x @ lin_l_w.T + b   [N,128]
__device__ float g_s1[(size_t)MAX_N * 4];    // a1 logits per node  [N,4]
__device__ float g_s2[(size_t)MAX_N * 4];    // a2 logits per node  [N,4]
__device__ int   g_off[MAX_N + 1];           // CSR offsets of sorted row

// ---------------- fp32 tiled SGEMM: C[M,128] = A[M,256] @ W[128,256]^T + bias ----
__global__ void __launch_bounds__(256)
sgemm_k(const float* __restrict__ A, const float* __restrict__ W,
        const float* __restrict__ bias, float* __restrict__ C, int M)
{
    __shared__ float As[2][16][128];
    __shared__ float Bs[2][16][128];

    const int tid = threadIdx.x;
    const int bm  = blockIdx.x * 128;

    // micro-tile: 4+4 split rows/cols (reduces LDS bank conflicts)
    const int ra = (tid >> 4) * 4;   // 0..60
    const int ca = (tid & 15) * 4;   // 0..60

    // loader mapping: 2 float4 of A rows + 2 float4 of W rows per thread
    const int r0 = tid >> 2;         // 0..63
    const int r1 = r0 + 64;
    const int kq = (tid & 3) << 2;   // 0,4,8,12

    float acc[8][8];
#pragma unroll
    for (int i = 0; i < 8; i++)
#pragma unroll
        for (int j = 0; j < 8; j++) acc[i][j] = 0.f;

    // prologue: tile 0
    {
        float4 va0 = (bm + r0 < M) ? *(const float4*)(A + (size_t)(bm + r0) * K_DIM + kq) : make_float4(0,0,0,0);
        float4 va1 = (bm + r1 < M) ? *(const float4*)(A + (size_t)(bm + r1) * K_DIM + kq) : make_float4(0,0,0,0);
        float4 vb0 = *(const float4*)(W + (size_t)r0 * K_DIM + kq);
        float4 vb1 = *(const float4*)(W + (size_t)r1 * K_DIM + kq);
        As[0][kq+0][r0]=va0.x; As[0][kq+1][r0]=va0.y; As[0][kq+2][r0]=va0.z; As[0][kq+3][r0]=va0.w;
        As[0][kq+0][r1]=va1.x; As[0][kq+1][r1]=va1.y; As[0][kq+2][r1]=va1.z; As[0][kq+3][r1]=va1.w;
        Bs[0][kq+0][r0]=vb0.x; Bs[0][kq+1][r0]=vb0.y; Bs[0][kq+2][r0]=vb0.z; Bs[0][kq+3][r0]=vb0.w;
        Bs[0][kq+0][r1]=vb1.x; Bs[0][kq+1][r1]=vb1.y; Bs[0][kq+2][r1]=vb1.z; Bs[0][kq+3][r1]=vb1.w;
    }
    __syncthreads();

    for (int kt = 0; kt < 16; kt++) {
        const int buf = kt & 1;
        float4 na0, na1, nb0, nb1;
        if (kt < 15) {
            const int kb = (kt + 1) * 16 + kq;
            na0 = (bm + r0 < M) ? *(const float4*)(A + (size_t)(bm + r0) * K_DIM + kb) : make_float4(0,0,0,0);
            na1 = (bm + r1 < M) ? *(const float4*)(A + (size_t)(bm + r1) * K_DIM + kb) : make_float4(0,0,0,0);
            nb0 = *(const float4*)(W + (size_t)r0 * K_DIM + kb);
            nb1 = *(const float4*)(W + (size_t)r1 * K_DIM + kb);
        }
#pragma unroll
        for (int k = 0; k < 16; k++) {
            float4 a0 = *(const float4*)&As[buf][k][ra];
            float4 a1 = *(const float4*)&As[buf][k][ra + 64];
            float4 b0 = *(const float4*)&Bs[buf][k][ca];
            float4 b1 = *(const float4*)&Bs[buf][k][ca + 64];
            float a[8] = {a0.x,a0.y,a0.z,a0.w, a1.x,a1.y,a1.z,a1.w};
            float b[8] = {b0.x,b0.y,b0.z,b0.w, b1.x,b1.y,b1.z,b1.w};
#pragma unroll
            for (int i = 0; i < 8; i++)
#pragma unroll
                for (int j = 0; j < 8; j++) acc[i][j] += a[i] * b[j];
        }
        if (kt < 15) {
            const int nb = buf ^ 1;
            As[nb][kq+0][r0]=na0.x; As[nb][kq+1][r0]=na0.y; As[nb][kq+2][r0]=na0.z; As[nb][kq+3][r0]=na0.w;
            As[nb][kq+0][r1]=na1.x; As[nb][kq+1][r1]=na1.y; As[nb][kq+2][r1]=na1.z; As[nb][kq+3][r1]=na1.w;
            Bs[nb][kq+0][r0]=nb0.x; Bs[nb][kq+1][r0]=nb0.y; Bs[nb][kq+2][r0]=nb0.z; Bs[nb][kq+3][r0]=nb0.w;
            Bs[nb][kq+0][r1]=nb1.x; Bs[nb][kq+1][r1]=nb1.y; Bs[nb][kq+2][r1]=nb1.z; Bs[nb][kq+3][r1]=nb1.w;
        }
        __syncthreads();
    }

    // epilogue: bias + store
    float bv[8];
#pragma unroll
    for (int j = 0; j < 8; j++) bv[j] = bias[ca + (j < 4 ? j : 60 + j)];
#pragma unroll
    for (int i = 0; i < 8; i++) {
        const int gr = bm + ra + (i < 4 ? i : 60 + i);
        if (gr < M) {
            float4 o0 = make_float4(acc[i][0]+bv[0], acc[i][1]+bv[1], acc[i][2]+bv[2], acc[i][3]+bv[3]);
            float4 o1 = make_float4(acc[i][4]+bv[4], acc[i][5]+bv[5], acc[i][6]+bv[6], acc[i][7]+bv[7]);
            *(float4*)(C + (size_t)gr * HD + ca)      = o0;
            *(float4*)(C + (size_t)gr * HD + ca + 64) = o1;
        }
    }
}

// ---------------- attention logits: s1[n,h], s2[n,h] (one warp per node) -------
__global__ void __launch_bounds__(256)
logits_k(const float* __restrict__ x,
         const float* __restrict__ a1w, const float* __restrict__ a1b,
         const float* __restrict__ a2w, const float* __restrict__ a2b,
         int n)
{
    __shared__ float ws[8][K_DIM];
    for (int i = threadIdx.x; i < 4 * K_DIM; i += blockDim.x) {
        ws[i >> 8][i & 255]       = a1w[i];
        ws[4 + (i >> 8)][i & 255] = a2w[i];
    }
    __syncthreads();

    const int warp_id = (blockIdx.x * blockDim.x + threadIdx.x) >> 5;
    const int lane = threadIdx.x & 31;
    if (warp_id >= n) return;

    const float* xr = x + (size_t)warp_id * K_DIM;
    float xv[8];
#pragma unroll
    for (int j = 0; j < 8; j++) xv[j] = xr[lane + 32 * j];

#pragma unroll
    for (int h = 0; h < 8; h++) {
        float p = 0.f;
#pragma unroll
        for (int j = 0; j < 8; j++) p += xv[j] * ws[h][lane + 32 * j];
#pragma unroll
        for (int o = 16; o; o >>= 1) p += __shfl_xor_sync(0xffffffffu, p, o);
        if (lane == 0) {
            if (h < 4) g_s1[(size_t)warp_id * 4 + h]     = p + a1b[h];
            else       g_s2[(size_t)warp_id * 4 + h - 4] = p + a2b[h - 4];
        }
    }
}

// ---------------- CSR offsets via binary search on sorted row ------------------
__global__ void offsets_k(const int* __restrict__ row, int n, int e)
{
    const int i = blockIdx.x * blockDim.x + threadIdx.x;
    if (i > n) return;
    int lo = 0, hi = e;
    while (lo < hi) {
        const int mid = (lo + hi) >> 1;
        if (row[mid] < i) lo = mid + 1; else hi = mid;
    }
    g_off[i] = lo;
}

// ---------------- segment softmax + weighted aggregation (warp per node) -------
__global__ void __launch_bounds__(256)
agg_k(const int* __restrict__ col, float* __restrict__ out, int n)
{
    const int warp_id = (blockIdx.x * blockDim.x + threadIdx.x) >> 5;
    const int lane = threadIdx.x & 31;
    if (warp_id >= n) return;

    const int e0 = g_off[warp_id];
    const int e1 = g_off[warp_id + 1];

    const float s1h = (lane < 4) ? g_s1[(size_t)warp_id * 4 + lane] : 0.f;

    // pass 1: per-head segment max (lanes 0..3 own heads 0..3)
    float m = -INFINITY;
    for (int e = e0; e < e1; ++e) {
        const int c = col[e];
        if (lane < 4) {
            const float a = s1h + g_s2[(size_t)c * 4 + lane];
            m = fmaxf(m, a);
        }
    }

    // pass 2: exp, sum, weighted aggregation of xw[col]
    float acc0 = 0.f, acc1 = 0.f, acc2 = 0.f, acc3 = 0.f, sum = 0.f;
#pragma unroll 2
    for (int e = e0; e < e1; ++e) {
        const int c = col[e];
        float w = 0.f;
        if (lane < 4) {
            const float a = s1h + g_s2[(size_t)c * 4 + lane];
            w = __expf(a - m);
            sum += w;
        }
        const float w0 = __shfl_sync(0xffffffffu, w, 0);
        const float w1 = __shfl_sync(0xffffffffu, w, 1);
        const float w2 = __shfl_sync(0xffffffffu, w, 2);
        const float w3 = __shfl_sync(0xffffffffu, w, 3);
        const float* xr = g_xw + (size_t)c * HD;
        acc0 += w0 * xr[lane];
        acc1 += w1 * xr[32 + lane];
        acc2 += w2 * xr[64 + lane];
        acc3 += w3 * xr[96 + lane];
    }

    const float i0 = 1.f / (__shfl_sync(0xffffffffu, sum, 0) + 1e-16f);
    const float i1 = 1.f / (__shfl_sync(0xffffffffu, sum, 1) + 1e-16f);
    const float i2 = 1.f / (__shfl_sync(0xffffffffu, sum, 2) + 1e-16f);
    const float i3 = 1.f / (__shfl_sync(0xffffffffu, sum, 3) + 1e-16f);

    float* o = out + (size_t)warp_id * HD;
    o[lane]      += acc0 * i0;
    o[32 + lane] += acc1 * i1;
    o[64 + lane] += acc2 * i2;
    o[96 + lane] += acc3 * i3;
}

// ---------------- launch --------------------------------------------------------
extern "C" void kernel_launch(void* const* d_in, const int* in_sizes, int n_in,
                              void* d_out, int out_size)
{
    const float* x   = (const float*)d_in[0];
    const int*   row = (const int*)d_in[1];
    const int*   col = (const int*)d_in[2];
    const float* a1w = (const float*)d_in[3];
    const float* a1b = (const float*)d_in[4];
    const float* a2w = (const float*)d_in[5];
    const float* a2b = (const float*)d_in[6];
    const float* llw = (const float*)d_in[7];
    const float* llb = (const float*)d_in[8];
    const float* lrw = (const float*)d_in[9];
    const float* lrb = (const float*)d_in[10];

    const int n = in_sizes[0] / K_DIM;
    const int e = in_sizes[1];

    float* xw = nullptr;
    cudaGetSymbolAddress((void**)&xw, g_xw);
    float* outp = (float*)d_out;

    const int mg = (n + 127) / 128;
    sgemm_k<<<mg, 256>>>(x, llw, llb, xw,   n);   // xw = x @ lin_l^T + b_l
    sgemm_k<<<mg, 256>>>(x, lrw, lrb, outp, n);   // out = x @ lin_r^T + b_r (base)
    logits_k<<<(n * 32 + 255) / 256, 256>>>(x, a1w, a1b, a2w, a2b, n);
    offsets_k<<<(n + 1 + 255) / 256, 256>>>(row, n, e);
    agg_k<<<(n * 32 + 255) / 256, 256>>>(col, outp, n);
}

// round 2
// speedup vs baseline: 1.0831x; 1.0831x over previous
#include <cuda_runtime.h>
#include <math.h>

#define K_DIM 256
#define HD 128
#define MAX_N 100000
#define MAX_E 1600000

typedef unsigned long long u64;

// ---------------- scratch (static device arrays; no allocation) ----------------
__device__ float g_xw[(size_t)MAX_N * HD];   // x @ lin_l_w.T + b   [N,128]
__device__ float g_s1[(size_t)MAX_N * 4];    // a1 logits per node  [N,4]
__device__ float g_s2[(size_t)MAX_N * 4];    // a2 logits per node  [N,4]
__device__ int   g_off[MAX_N + 1];           // CSR offsets of sorted row

// ---------------- packed f32x2 helpers (Blackwell FFMA2) -----------------------
__device__ __forceinline__ u64 pack2(float v) {
    u64 r;
    asm("mov.b64 %0, {%1, %1};" : "=l"(r) : "f"(v));
    return r;
}
__device__ __forceinline__ void fma2(u64 &acc, u64 a, u64 b) {
    asm("fma.rn.f32x2 %0, %1, %2, %0;" : "+l"(acc) : "l"(a), "l"(b));
}

// ---------------- f32x2 tiled SGEMM: C[M,128] = A[M,256] @ W[128,256]^T + bias --
__global__ void __launch_bounds__(256)
sgemm_k(const float* __restrict__ A, const float* __restrict__ W,
        const float* __restrict__ bias, float* __restrict__ C, int M)
{
    __shared__ float As[2][16][128];
    __shared__ float Bs[2][16][128];

    const int tid = threadIdx.x;
    const int bm  = blockIdx.x * 128;

    // micro-tile: 4+4 split rows/cols
    const int ra = (tid >> 4) * 4;   // 0..60
    const int ca = (tid & 15) * 4;   // 0..60

    // loader mapping
    const int r0 = tid >> 2;         // 0..63
    const int r1 = r0 + 64;
    const int kq = (tid & 3) << 2;   // 0,4,8,12

    // accumulators: 8 rows x 4 column-pairs, packed f32x2
    u64 acc[8][4];
#pragma unroll
    for (int i = 0; i < 8; i++)
#pragma unroll
        for (int j = 0; j < 4; j++) acc[i][j] = 0ULL;

    // prologue: tile 0
    {
        float4 va0 = (bm + r0 < M) ? *(const float4*)(A + (size_t)(bm + r0) * K_DIM + kq) : make_float4(0,0,0,0);
        float4 va1 = (bm + r1 < M) ? *(const float4*)(A + (size_t)(bm + r1) * K_DIM + kq) : make_float4(0,0,0,0);
        float4 vb0 = *(const float4*)(W + (size_t)r0 * K_DIM + kq);
        float4 vb1 = *(const float4*)(W + (size_t)r1 * K_DIM + kq);
        As[0][kq+0][r0]=va0.x; As[0][kq+1][r0]=va0.y; As[0][kq+2][r0]=va0.z; As[0][kq+3][r0]=va0.w;
        As[0][kq+0][r1]=va1.x; As[0][kq+1][r1]=va1.y; As[0][kq+2][r1]=va1.z; As[0][kq+3][r1]=va1.w;
        Bs[0][kq+0][r0]=vb0.x; Bs[0][kq+1][r0]=vb0.y; Bs[0][kq+2][r0]=vb0.z; Bs[0][kq+3][r0]=vb0.w;
        Bs[0][kq+0][r1]=vb1.x; Bs[0][kq+1][r1]=vb1.y; Bs[0][kq+2][r1]=vb1.z; Bs[0][kq+3][r1]=vb1.w;
    }
    __syncthreads();

    for (int kt = 0; kt < 16; kt++) {
        const int buf = kt & 1;
        float4 na0, na1, nb0, nb1;
        if (kt < 15) {
            const int kb = (kt + 1) * 16 + kq;
            na0 = (bm + r0 < M) ? *(const float4*)(A + (size_t)(bm + r0) * K_DIM + kb) : make_float4(0,0,0,0);
            na1 = (bm + r1 < M) ? *(const float4*)(A + (size_t)(bm + r1) * K_DIM + kb) : make_float4(0,0,0,0);
            nb0 = *(const float4*)(W + (size_t)r0 * K_DIM + kb);
            nb1 = *(const float4*)(W + (size_t)r1 * K_DIM + kb);
        }
#pragma unroll
        for (int k = 0; k < 16; k++) {
            float4 a0 = *(const float4*)&As[buf][k][ra];
            float4 a1 = *(const float4*)&As[buf][k][ra + 64];
            float4 b0 = *(const float4*)&Bs[buf][k][ca];
            float4 b1 = *(const float4*)&Bs[buf][k][ca + 64];
            // b column pairs: reinterpret float4 as two packed f32x2 each
            u64 bp[4];
            bp[0] = ((const u64*)&b0)[0];
            bp[1] = ((const u64*)&b0)[1];
            bp[2] = ((const u64*)&b1)[0];
            bp[3] = ((const u64*)&b1)[1];
            // a broadcast into both f32x2 lanes
            float av[8] = {a0.x,a0.y,a0.z,a0.w, a1.x,a1.y,a1.z,a1.w};
            u64 aa[8];
#pragma unroll
            for (int i = 0; i < 8; i++) aa[i] = pack2(av[i]);
#pragma unroll
            for (int i = 0; i < 8; i++)
#pragma unroll
                for (int j = 0; j < 4; j++) fma2(acc[i][j], aa[i], bp[j]);
        }
        if (kt < 15) {
            const int nb = buf ^ 1;
            As[nb][kq+0][r0]=na0.x; As[nb][kq+1][r0]=na0.y; As[nb][kq+2][r0]=na0.z; As[nb][kq+3][r0]=na0.w;
            As[nb][kq+0][r1]=na1.x; As[nb][kq+1][r1]=na1.y; As[nb][kq+2][r1]=na1.z; As[nb][kq+3][r1]=na1.w;
            Bs[nb][kq+0][r0]=nb0.x; Bs[nb][kq+1][r0]=nb0.y; Bs[nb][kq+2][r0]=nb0.z; Bs[nb][kq+3][r0]=nb0.w;
            Bs[nb][kq+0][r1]=nb1.x; Bs[nb][kq+1][r1]=nb1.y; Bs[nb][kq+2][r1]=nb1.z; Bs[nb][kq+3][r1]=nb1.w;
        }
        __syncthreads();
    }

    // epilogue: bias + store
    float bv[8];
#pragma unroll
    for (int j = 0; j < 8; j++) bv[j] = bias[ca + (j < 4 ? j : 60 + j)];
#pragma unroll
    for (int i = 0; i < 8; i++) {
        const int gr = bm + ra + (i < 4 ? i : 60 + i);
        if (gr < M) {
            union { u64 u; float2 f; } c0, c1, c2, c3;
            c0.u = acc[i][0]; c1.u = acc[i][1]; c2.u = acc[i][2]; c3.u = acc[i][3];
            float4 o0 = make_float4(c0.f.x+bv[0], c0.f.y+bv[1], c1.f.x+bv[2], c1.f.y+bv[3]);
            float4 o1 = make_float4(c2.f.x+bv[4], c2.f.y+bv[5], c3.f.x+bv[6], c3.f.y+bv[7]);
            *(float4*)(C + (size_t)gr * HD + ca)      = o0;
            *(float4*)(C + (size_t)gr * HD + ca + 64) = o1;
        }
    }
}

// ---------------- attention logits: s1[n,h], s2[n,h] (one warp per node) -------
__global__ void __launch_bounds__(256)
logits_k(const float* __restrict__ x,
         const float* __restrict__ a1w, const float* __restrict__ a1b,
         const float* __restrict__ a2w, const float* __restrict__ a2b,
         int n)
{
    __shared__ float ws[8][K_DIM];
    for (int i = threadIdx.x; i < 4 * K_DIM; i += blockDim.x) {
        ws[i >> 8][i & 255]       = a1w[i];
        ws[4 + (i >> 8)][i & 255] = a2w[i];
    }
    __syncthreads();

    const int warp_id = (blockIdx.x * blockDim.x + threadIdx.x) >> 5;
    const int lane = threadIdx.x & 31;
    if (warp_id >= n) return;

    const float* xr = x + (size_t)warp_id * K_DIM;
    float xv[8];
#pragma unroll
    for (int j = 0; j < 8; j++) xv[j] = xr[lane + 32 * j];

#pragma unroll
    for (int h = 0; h < 8; h++) {
        float p = 0.f;
#pragma unroll
        for (int j = 0; j < 8; j++) p += xv[j] * ws[h][lane + 32 * j];
#pragma unroll
        for (int o = 16; o; o >>= 1) p += __shfl_xor_sync(0xffffffffu, p, o);
        if (lane == 0) {
            if (h < 4) g_s1[(size_t)warp_id * 4 + h]     = p + a1b[h];
            else       g_s2[(size_t)warp_id * 4 + h - 4] = p + a2b[h - 4];
        }
    }
}

// ---------------- CSR offsets via binary search on sorted row ------------------
__global__ void offsets_k(const int* __restrict__ row, int n, int e)
{
    const int i = blockIdx.x * blockDim.x + threadIdx.x;
    if (i > n) return;
    int lo = 0, hi = e;
    while (lo < hi) {
        const int mid = (lo + hi) >> 1;
        if (row[mid] < i) lo = mid + 1; else hi = mid;
    }
    g_off[i] = lo;
}

// ---------------- segment softmax + weighted aggregation (warp per node) -------
__global__ void __launch_bounds__(256)
agg_k(const int* __restrict__ col, float* __restrict__ out, int n)
{
    const int warp_id = (blockIdx.x * blockDim.x + threadIdx.x) >> 5;
    const int lane = threadIdx.x & 31;
    if (warp_id >= n) return;

    const int e0 = g_off[warp_id];
    const int e1 = g_off[warp_id + 1];

    const float s1h = (lane < 4) ? g_s1[(size_t)warp_id * 4 + lane] : 0.f;

    // pass 1: per-head segment max (lanes 0..3 own heads 0..3)
    float m = -INFINITY;
    for (int e = e0; e < e1; ++e) {
        const int c = col[e];
        if (lane < 4) {
            const float a = s1h + g_s2[(size_t)c * 4 + lane];
            m = fmaxf(m, a);
        }
    }

    // pass 2: exp, sum, weighted aggregation of xw[col]
    float acc0 = 0.f, acc1 = 0.f, acc2 = 0.f, acc3 = 0.f, sum = 0.f;
#pragma unroll 2
    for (int e = e0; e < e1; ++e) {
        const int c = col[e];
        float w = 0.f;
        if (lane < 4) {
            const float a = s1h + g_s2[(size_t)c * 4 + lane];
            w = __expf(a - m);
            sum += w;
        }
        const float w0 = __shfl_sync(0xffffffffu, w, 0);
        const float w1 = __shfl_sync(0xffffffffu, w, 1);
        const float w2 = __shfl_sync(0xffffffffu, w, 2);
        const float w3 = __shfl_sync(0xffffffffu, w, 3);
        const float* xr = g_xw + (size_t)c * HD;
        acc0 += w0 * xr[lane];
        acc1 += w1 * xr[32 + lane];
        acc2 += w2 * xr[64 + lane];
        acc3 += w3 * xr[96 + lane];
    }

    const float i0 = 1.f / (__shfl_sync(0xffffffffu, sum, 0) + 1e-16f);
    const float i1 = 1.f / (__shfl_sync(0xffffffffu, sum, 1) + 1e-16f);
    const float i2 = 1.f / (__shfl_sync(0xffffffffu, sum, 2) + 1e-16f);
    const float i3 = 1.f / (__shfl_sync(0xffffffffu, sum, 3) + 1e-16f);

    float* o = out + (size_t)warp_id * HD;
    o[lane]      += acc0 * i0;
    o[32 + lane] += acc1 * i1;
    o[64 + lane] += acc2 * i2;
    o[96 + lane] += acc3 * i3;
}

// ---------------- launch --------------------------------------------------------
extern "C" void kernel_launch(void* const* d_in, const int* in_sizes, int n_in,
                              void* d_out, int out_size)
{
    const float* x   = (const float*)d_in[0];
    const int*   row = (const int*)d_in[1];
    const int*   col = (const int*)d_in[2];
    const float* a1w = (const float*)d_in[3];
    const float* a1b = (const float*)d_in[4];
    const float* a2w = (const float*)d_in[5];
    const float* a2b = (const float*)d_in[6];
    const float* llw = (const float*)d_in[7];
    const float* llb = (const float*)d_in[8];
    const float* lrw = (const float*)d_in[9];
    const float* lrb = (const float*)d_in[10];

    const int n = in_sizes[0] / K_DIM;
    const int e = in_sizes[1];

    float* xw = nullptr;
    cudaGetSymbolAddress((void**)&xw, g_xw);
    float* outp = (float*)d_out;

    const int mg = (n + 127) / 128;
    sgemm_k<<<mg, 256>>>(x, llw, llb, xw,   n);   // xw = x @ lin_l^T + b_l
    sgemm_k<<<mg, 256>>>(x, lrw, lrb, outp, n);   // out = x @ lin_r^T + b_r (base)
    logits_k<<<(n * 32 + 255) / 256, 256>>>(x, a1w, a1b, a2w, a2b, n);
    offsets_k<<<(n + 1 + 255) / 256, 256>>>(row, n, e);
    agg_k<<<(n * 32 + 255) / 256, 256>>>(col, outp, n);
}

// round 4
// speedup vs baseline: 1.6694x; 1.5412x over previous
#include <cuda_runtime.h>
#include <cuda_bf16.h>
#include <math.h>
#include <stdint.h>

#define K_DIM 256
#define HD 128
#define MAX_N 100000
#define MAX_E 1600000

// ---------------- scratch (static device arrays; no allocation) ----------------
__device__ float g_xw[(size_t)MAX_N * HD];        // x @ lin_l^T + b    [N,128]
__device__ float g_s1[(size_t)MAX_N * 4];         // a1 logits per node [N,4]
__device__ float g_s2[(size_t)MAX_N * 4];         // a2 logits per node [N,4]
__device__ int   g_off[MAX_N + 1];                // CSR offsets
__device__ __nv_bfloat16 g_bh[256 * 256];         // W_cat hi  [256 out][256 k]
__device__ __nv_bfloat16 g_bl[256 * 256];         // W_cat lo
__device__ float g_bc[256];                       // bias cat

// ---------------- PTX helpers ---------------------------------------------------
__device__ __forceinline__ uint32_t smem_u32(const void* p) {
    uint32_t a;
    asm("{ .reg .u64 t; cvta.to.shared.u64 t, %1; cvt.u32.u64 %0, t; }" : "=r"(a) : "l"(p));
    return a;
}
__device__ __forceinline__ void ldsm4(uint32_t* r, uint32_t addr) {
    asm volatile("ldmatrix.sync.aligned.m8n8.x4.shared.b16 {%0,%1,%2,%3}, [%4];"
                 : "=r"(r[0]), "=r"(r[1]), "=r"(r[2]), "=r"(r[3]) : "r"(addr));
}
__device__ __forceinline__ void mma_bf16(float* c, const uint32_t* a, uint32_t b0, uint32_t b1) {
    asm volatile(
        "mma.sync.aligned.m16n8k16.row.col.f32.bf16.bf16.f32 "
        "{%0,%1,%2,%3}, {%4,%5,%6,%7}, {%8,%9}, {%0,%1,%2,%3};"
        : "+f"(c[0]), "+f"(c[1]), "+f"(c[2]), "+f"(c[3])
        : "r"(a[0]), "r"(a[1]), "r"(a[2]), "r"(a[3]), "r"(b0), "r"(b1));
}

// ---------------- weight prep: fp32 -> bf16 hi/lo, concat lin_l|lin_r -----------
__global__ void wprep_k(const float* __restrict__ llw, const float* __restrict__ llb,
                        const float* __restrict__ lrw, const float* __restrict__ lrb)
{
    const int idx = blockIdx.x * blockDim.x + threadIdx.x;   // 0..65535
    const int n = idx >> 8, k = idx & 255;
    const float v = (n < 128) ? llw[n * 256 + k] : lrw[(n - 128) * 256 + k];
    const __nv_bfloat16 hi = __float2bfloat16(v);
    const __nv_bfloat16 lo = __float2bfloat16(v - __bfloat162float(hi));
    g_bh[idx] = hi;
    g_bl[idx] = lo;
    if (idx < 256) g_bc[idx] = (idx < 128) ? llb[idx] : lrb[idx - 128];
}

// ---------------- HMMA bf16-split GEMM: C[128,128] per CTA ----------------------
// grid = (ceil(M/128), 2). y=0 -> g_xw (lin_l), y=1 -> out (lin_r).
// smem row stride 40 bf16 (80B): conflict-free ldmatrix.
#define LDS_STRIDE 40

__global__ void __launch_bounds__(256, 2)
gemm_mma_k(const float* __restrict__ A, float* __restrict__ outp, int M)
{
    __shared__ __align__(16) __nv_bfloat16 Ah[128 * LDS_STRIDE];
    __shared__ __align__(16) __nv_bfloat16 Al[128 * LDS_STRIDE];
    __shared__ __align__(16) __nv_bfloat16 Bh[128 * LDS_STRIDE];
    __shared__ __align__(16) __nv_bfloat16 Bl[128 * LDS_STRIDE];

    const int tid = threadIdx.x;
    const int wid = tid >> 5;
    const int lane = tid & 31;
    const int bm = blockIdx.x * 128;
    const int by = blockIdx.y;
    const int warp_m = wid & 3;          // 4 warps along M (32 rows each)
    const int warp_n = wid >> 2;         // 2 warps along N (64 cols each)

    float acc[2][8][4];
#pragma unroll
    for (int i = 0; i < 2; i++)
#pragma unroll
        for (int j = 0; j < 8; j++)
#pragma unroll
            for (int q = 0; q < 4; q++) acc[i][j][q] = 0.f;

    // loader mapping: each thread owns (row, 16-k half)
    const int lrow = tid >> 1;
    const int lhalf = tid & 1;
    const bool avalid = (bm + lrow) < M;
    const float* ag = A + (size_t)(bm + lrow) * K_DIM + lhalf * 16;
    const __nv_bfloat16* bgh = g_bh + (size_t)(by * 128 + lrow) * 256 + lhalf * 16;
    const __nv_bfloat16* bgl = g_bl + (size_t)(by * 128 + lrow) * 256 + lhalf * 16;

    const uint32_t ah_s = smem_u32(Ah);
    const uint32_t al_s = smem_u32(Al);
    const uint32_t bh_s = smem_u32(Bh);
    const uint32_t bl_s = smem_u32(Bl);

    char* ah_p = (char*)Ah; char* al_p = (char*)Al;
    char* bh_p = (char*)Bh; char* bl_p = (char*)Bl;
    const uint32_t st_off = lrow * (LDS_STRIDE * 2) + lhalf * 32;   // bytes

    for (int c = 0; c < 8; c++) {
        if (c) __syncthreads();   // previous chunk fully consumed

        // ---- A chunk: fp32 -> bf16 hi/lo (128 rows x 32 k) ----
#pragma unroll
        for (int q = 0; q < 4; q++) {
            float4 f = avalid ? *(const float4*)(ag + c * 32 + q * 4) : make_float4(0, 0, 0, 0);
            __nv_bfloat162 h0 = __floats2bfloat162_rn(f.x, f.y);
            __nv_bfloat162 h1 = __floats2bfloat162_rn(f.z, f.w);
            float2 fh0 = __bfloat1622float2(h0), fh1 = __bfloat1622float2(h1);
            __nv_bfloat162 l0 = __floats2bfloat162_rn(f.x - fh0.x, f.y - fh0.y);
            __nv_bfloat162 l1 = __floats2bfloat162_rn(f.z - fh1.x, f.w - fh1.y);
            uint2 hv, lv;
            hv.x = *(uint32_t*)&h0; hv.y = *(uint32_t*)&h1;
            lv.x = *(uint32_t*)&l0; lv.y = *(uint32_t*)&l1;
            *(uint2*)(ah_p + st_off + q * 8) = hv;
            *(uint2*)(al_p + st_off + q * 8) = lv;
        }
        // ---- B chunk: pre-converted bf16 (128 n-rows x 32 k) ----
        {
            const uint4* sh = (const uint4*)(bgh + c * 32);
            const uint4* sl = (const uint4*)(bgl + c * 32);
            *(uint4*)(bh_p + st_off)      = sh[0];
            *(uint4*)(bh_p + st_off + 16) = sh[1];
            *(uint4*)(bl_p + st_off)      = sl[0];
            *(uint4*)(bl_p + st_off + 16) = sl[1];
        }
        __syncthreads();

        // ---- MMA: 2 k16 steps ----
#pragma unroll
        for (int ks = 0; ks < 2; ks++) {
            const uint32_t kb = ks * 32 + (lane >> 4) * 16;   // byte offset within row pair
            uint32_t a_h[2][4], a_l[2][4];
#pragma unroll
            for (int mt = 0; mt < 2; mt++) {
                const uint32_t ro = (warp_m * 32 + mt * 16 + (lane & 15)) * (LDS_STRIDE * 2) + kb;
                ldsm4(a_h[mt], ah_s + ro);
                ldsm4(a_l[mt], al_s + ro);
            }
#pragma unroll
            for (int nt = 0; nt < 4; nt++) {
                const uint32_t ro = (warp_n * 64 + nt * 16 + (lane & 15)) * (LDS_STRIDE * 2) + kb;
                uint32_t b_h[4], b_l[4];
                ldsm4(b_h, bh_s + ro);
                ldsm4(b_l, bl_s + ro);
#pragma unroll
                for (int mt = 0; mt < 2; mt++) {
                    mma_bf16(acc[mt][nt * 2],     a_h[mt], b_h[0], b_h[2]);
                    mma_bf16(acc[mt][nt * 2 + 1], a_h[mt], b_h[1], b_h[3]);
                    mma_bf16(acc[mt][nt * 2],     a_h[mt], b_l[0], b_l[2]);
                    mma_bf16(acc[mt][nt * 2 + 1], a_h[mt], b_l[1], b_l[3]);
                    mma_bf16(acc[mt][nt * 2],     a_l[mt], b_h[0], b_h[2]);
                    mma_bf16(acc[mt][nt * 2 + 1], a_l[mt], b_h[1], b_h[3]);
                }
            }
        }
    }

    // ---- epilogue: bias + store ----
    float* dst = (by == 0) ? g_xw : outp;
    const float* bias = g_bc + by * 128;
#pragma unroll
    for (int mt = 0; mt < 2; mt++) {
        const int r0 = bm + warp_m * 32 + mt * 16 + (lane >> 2);
#pragma unroll
        for (int nt2 = 0; nt2 < 8; nt2++) {
            const int cc = warp_n * 64 + nt2 * 8 + (lane & 3) * 2;
            const float b0 = bias[cc], b1 = bias[cc + 1];
            if (r0 < M) {
                float2 v = make_float2(acc[mt][nt2][0] + b0, acc[mt][nt2][1] + b1);
                *(float2*)(dst + (size_t)r0 * HD + cc) = v;
            }
            if (r0 + 8 < M) {
                float2 v = make_float2(acc[mt][nt2][2] + b0, acc[mt][nt2][3] + b1);
                *(float2*)(dst + (size_t)(r0 + 8) * HD + cc) = v;
            }
        }
    }
}

// ---------------- attention logits (one warp per node) -------------------------
__global__ void __launch_bounds__(256)
logits_k(const float* __restrict__ x,
         const float* __restrict__ a1w, const float* __restrict__ a1b,
         const float* __restrict__ a2w, const float* __restrict__ a2b,
         int n)
{
    __shared__ float ws[8][K_DIM];
    for (int i = threadIdx.x; i < 4 * K_DIM; i += blockDim.x) {
        ws[i >> 8][i & 255]       = a1w[i];
        ws[4 + (i >> 8)][i & 255] = a2w[i];
    }
    __syncthreads();

    const int warp_id = (blockIdx.x * blockDim.x + threadIdx.x) >> 5;
    const int lane = threadIdx.x & 31;
    if (warp_id >= n) return;

    const float* xr = x + (size_t)warp_id * K_DIM;
    float xv[8];
#pragma unroll
    for (int j = 0; j < 8; j++) xv[j] = xr[lane + 32 * j];

#pragma unroll
    for (int h = 0; h < 8; h++) {
        float p = 0.f;
#pragma unroll
        for (int j = 0; j < 8; j++) p += xv[j] * ws[h][lane + 32 * j];
#pragma unroll
        for (int o = 16; o; o >>= 1) p += __shfl_xor_sync(0xffffffffu, p, o);
        if (lane == 0) {
            if (h < 4) g_s1[(size_t)warp_id * 4 + h]     = p + a1b[h];
            else       g_s2[(size_t)warp_id * 4 + h - 4] = p + a2b[h - 4];
        }
    }
}

// ---------------- CSR offsets ----------------------------------------------------
__global__ void offsets_k(const int* __restrict__ row, int n, int e)
{
    const int i = blockIdx.x * blockDim.x + threadIdx.x;
    if (i > n) return;
    int lo = 0, hi = e;
    while (lo < hi) {
        const int mid = (lo + hi) >> 1;
        if (row[mid] < i) lo = mid + 1; else hi = mid;
    }
    g_off[i] = lo;
}

// ---------------- segment softmax + aggregation (warp per node) -----------------
__global__ void __launch_bounds__(256)
agg_k(const int* __restrict__ col, float* __restrict__ out, int n)
{
    const int warp_id = (blockIdx.x * blockDim.x + threadIdx.x) >> 5;
    const int lane = threadIdx.x & 31;
    if (warp_id >= n) return;

    const int e0 = g_off[warp_id];
    const int e1 = g_off[warp_id + 1];

    const float s1h = (lane < 4) ? g_s1[(size_t)warp_id * 4 + lane] : 0.f;

    float m = -INFINITY;
    for (int e = e0; e < e1; ++e) {
        const int c = col[e];
        if (lane < 4) m = fmaxf(m, s1h + g_s2[(size_t)c * 4 + lane]);
    }

    float acc0 = 0.f, acc1 = 0.f, acc2 = 0.f, acc3 = 0.f, sum = 0.f;
#pragma unroll 2
    for (int e = e0; e < e1; ++e) {
        const int c = col[e];
        float w = 0.f;
        if (lane < 4) {
            w = __expf(s1h + g_s2[(size_t)c * 4 + lane] - m);
            sum += w;
        }
        const float w0 = __shfl_sync(0xffffffffu, w, 0);
        const float w1 = __shfl_sync(0xffffffffu, w, 1);
        const float w2 = __shfl_sync(0xffffffffu, w, 2);
        const float w3 = __shfl_sync(0xffffffffu, w, 3);
        const float* xr = g_xw + (size_t)c * HD;
        acc0 += w0 * xr[lane];
        acc1 += w1 * xr[32 + lane];
        acc2 += w2 * xr[64 + lane];
        acc3 += w3 * xr[96 + lane];
    }

    const float i0 = 1.f / (__shfl_sync(0xffffffffu, sum, 0) + 1e-16f);
    const float i1 = 1.f / (__shfl_sync(0xffffffffu, sum, 1) + 1e-16f);
    const float i2 = 1.f / (__shfl_sync(0xffffffffu, sum, 2) + 1e-16f);
    const float i3 = 1.f / (__shfl_sync(0xffffffffu, sum, 3) + 1e-16f);

    float* o = out + (size_t)warp_id * HD;
    o[lane]      += acc0 * i0;
    o[32 + lane] += acc1 * i1;
    o[64 + lane] += acc2 * i2;
    o[96 + lane] += acc3 * i3;
}

// ---------------- launch ---------------------------------------------------------
extern "C" void kernel_launch(void* const* d_in, const int* in_sizes, int n_in,
                              void* d_out, int out_size)
{
    const float* x   = (const float*)d_in[0];
    const int*   row = (const int*)d_in[1];
    const int*   col = (const int*)d_in[2];
    const float* a1w = (const float*)d_in[3];
    const float* a1b = (const float*)d_in[4];
    const float* a2w = (const float*)d_in[5];
    const float* a2b = (const float*)d_in[6];
    const float* llw = (const float*)d_in[7];
    const float* llb = (const float*)d_in[8];
    const float* lrw = (const float*)d_in[9];
    const float* lrb = (const float*)d_in[10];

    const int n = in_sizes[0] / K_DIM;
    const int e = in_sizes[1];
    float* outp = (float*)d_out;

    wprep_k<<<256, 256>>>(llw, llb, lrw, lrb);
    offsets_k<<<(n + 1 + 255) / 256, 256>>>(row, n, e);
    logits_k<<<(n * 32 + 255) / 256, 256>>>(x, a1w, a1b, a2w, a2b, n);
    dim3 gg((n + 127) / 128, 2);
    gemm_mma_k<<<gg, 256>>>(x, outp, n);
    agg_k<<<(n * 32 + 255) / 256, 256>>>(col, outp, n);
}

// round 7
// speedup vs baseline: 1.8072x; 1.0826x over previous
#include <cuda_runtime.h>
#include <cuda_bf16.h>
#include <math.h>
#include <stdint.h>

#define K_DIM 256
#define HD 128
#define MAX_N 100000
#define MAX_E 1600000

// ---------------- scratch (static device arrays; no allocation) ----------------
__device__ float g_xw[(size_t)MAX_N * HD];        // x @ lin_l^T + b    [N,128]
__device__ float g_s1[(size_t)MAX_N * 4];         // a1 logits per node [N,4]
__device__ float g_s2[(size_t)MAX_N * 4];         // a2 logits per node [N,4]
__device__ int   g_off[MAX_N + 1];                // CSR offsets
__device__ __nv_bfloat16 g_bh[256 * 256];         // W_cat hi  [256 out][256 k]
__device__ __nv_bfloat16 g_bl[256 * 256];         // W_cat lo
__device__ float g_bc[256];                       // bias cat

// ---------------- PTX helpers ---------------------------------------------------
__device__ __forceinline__ uint32_t smem_u32(const void* p) {
    uint32_t a;
    asm("{ .reg .u64 t; cvta.to.shared.u64 t, %1; cvt.u32.u64 %0, t; }" : "=r"(a) : "l"(p));
    return a;
}
__device__ __forceinline__ void ldsm4(uint32_t* r, uint32_t addr) {
    asm volatile("ldmatrix.sync.aligned.m8n8.x4.shared.b16 {%0,%1,%2,%3}, [%4];"
                 : "=r"(r[0]), "=r"(r[1]), "=r"(r[2]), "=r"(r[3]) : "r"(addr));
}
__device__ __forceinline__ void mma_bf16(float* c, const uint32_t* a, uint32_t b0, uint32_t b1) {
    asm volatile(
        "mma.sync.aligned.m16n8k16.row.col.f32.bf16.bf16.f32 "
        "{%0,%1,%2,%3}, {%4,%5,%6,%7}, {%8,%9}, {%0,%1,%2,%3};"
        : "+f"(c[0]), "+f"(c[1]), "+f"(c[2]), "+f"(c[3])
        : "r"(a[0]), "r"(a[1]), "r"(a[2]), "r"(a[3]), "r"(b0), "r"(b1));
}

// ---------------- weight prep: fp32 -> bf16 hi/lo, concat lin_l|lin_r -----------
__global__ void wprep_k(const float* __restrict__ llw, const float* __restrict__ llb,
                        const float* __restrict__ lrw, const float* __restrict__ lrb)
{
    const int idx = blockIdx.x * blockDim.x + threadIdx.x;   // 0..65535
    const int n = idx >> 8, k = idx & 255;
    const float v = (n < 128) ? llw[n * 256 + k] : lrw[(n - 128) * 256 + k];
    const __nv_bfloat16 hi = __float2bfloat16(v);
    const __nv_bfloat16 lo = __float2bfloat16(v - __bfloat162float(hi));
    g_bh[idx] = hi;
    g_bl[idx] = lo;
    if (idx < 256) g_bc[idx] = (idx < 128) ? llb[idx] : lrb[idx - 128];
}

// ---------------- HMMA bf16-split GEMM: C[128,128] per CTA ----------------------
#define LDS_STRIDE 40

__global__ void __launch_bounds__(256, 2)
gemm_mma_k(const float* __restrict__ A, float* __restrict__ outp, int M)
{
    __shared__ __align__(16) __nv_bfloat16 Ah[128 * LDS_STRIDE];
    __shared__ __align__(16) __nv_bfloat16 Al[128 * LDS_STRIDE];
    __shared__ __align__(16) __nv_bfloat16 Bh[128 * LDS_STRIDE];
    __shared__ __align__(16) __nv_bfloat16 Bl[128 * LDS_STRIDE];

    const int tid = threadIdx.x;
    const int wid = tid >> 5;
    const int lane = tid & 31;
    const int bm = blockIdx.x * 128;
    const int by = blockIdx.y;
    const int warp_m = wid & 3;
    const int warp_n = wid >> 2;

    float acc[2][8][4];
#pragma unroll
    for (int i = 0; i < 2; i++)
#pragma unroll
        for (int j = 0; j < 8; j++)
#pragma unroll
            for (int q = 0; q < 4; q++) acc[i][j][q] = 0.f;

    const int lrow = tid >> 1;
    const int lhalf = tid & 1;
    const bool avalid = (bm + lrow) < M;
    const float* ag = A + (size_t)(bm + lrow) * K_DIM + lhalf * 16;
    const __nv_bfloat16* bgh = g_bh + (size_t)(by * 128 + lrow) * 256 + lhalf * 16;
    const __nv_bfloat16* bgl = g_bl + (size_t)(by * 128 + lrow) * 256 + lhalf * 16;

    const uint32_t ah_s = smem_u32(Ah);
    const uint32_t al_s = smem_u32(Al);
    const uint32_t bh_s = smem_u32(Bh);
    const uint32_t bl_s = smem_u32(Bl);

    char* ah_p = (char*)Ah; char* al_p = (char*)Al;
    char* bh_p = (char*)Bh; char* bl_p = (char*)Bl;
    const uint32_t st_off = lrow * (LDS_STRIDE * 2) + lhalf * 32;

    for (int c = 0; c < 8; c++) {
        if (c) __syncthreads();

#pragma unroll
        for (int q = 0; q < 4; q++) {
            float4 f = avalid ? *(const float4*)(ag + c * 32 + q * 4) : make_float4(0, 0, 0, 0);
            __nv_bfloat162 h0 = __floats2bfloat162_rn(f.x, f.y);
            __nv_bfloat162 h1 = __floats2bfloat162_rn(f.z, f.w);
            float2 fh0 = __bfloat1622float2(h0), fh1 = __bfloat1622float2(h1);
            __nv_bfloat162 l0 = __floats2bfloat162_rn(f.x - fh0.x, f.y - fh0.y);
            __nv_bfloat162 l1 = __floats2bfloat162_rn(f.z - fh1.x, f.w - fh1.y);
            uint2 hv, lv;
            hv.x = *(uint32_t*)&h0; hv.y = *(uint32_t*)&h1;
            lv.x = *(uint32_t*)&l0; lv.y = *(uint32_t*)&l1;
            *(uint2*)(ah_p + st_off + q * 8) = hv;
            *(uint2*)(al_p + st_off + q * 8) = lv;
        }
        {
            const uint4* sh = (const uint4*)(bgh + c * 32);
            const uint4* sl = (const uint4*)(bgl + c * 32);
            *(uint4*)(bh_p + st_off)      = sh[0];
            *(uint4*)(bh_p + st_off + 16) = sh[1];
            *(uint4*)(bl_p + st_off)      = sl[0];
            *(uint4*)(bl_p + st_off + 16) = sl[1];
        }
        __syncthreads();

#pragma unroll
        for (int ks = 0; ks < 2; ks++) {
            const uint32_t kb = ks * 32 + (lane >> 4) * 16;
            uint32_t a_h[2][4], a_l[2][4];
#pragma unroll
            for (int mt = 0; mt < 2; mt++) {
                const uint32_t ro = (warp_m * 32 + mt * 16 + (lane & 15)) * (LDS_STRIDE * 2) + kb;
                ldsm4(a_h[mt], ah_s + ro);
                ldsm4(a_l[mt], al_s + ro);
            }
#pragma unroll
            for (int nt = 0; nt < 4; nt++) {
                const uint32_t ro = (warp_n * 64 + nt * 16 + (lane & 15)) * (LDS_STRIDE * 2) + kb;
                uint32_t b_h[4], b_l[4];
                ldsm4(b_h, bh_s + ro);
                ldsm4(b_l, bl_s + ro);
#pragma unroll
                for (int mt = 0; mt < 2; mt++) {
                    mma_bf16(acc[mt][nt * 2],     a_h[mt], b_h[0], b_h[2]);
                    mma_bf16(acc[mt][nt * 2 + 1], a_h[mt], b_h[1], b_h[3]);
                    mma_bf16(acc[mt][nt * 2],     a_h[mt], b_l[0], b_l[2]);
                    mma_bf16(acc[mt][nt * 2 + 1], a_h[mt], b_l[1], b_l[3]);
                    mma_bf16(acc[mt][nt * 2],     a_l[mt], b_h[0], b_h[2]);
                    mma_bf16(acc[mt][nt * 2 + 1], a_l[mt], b_h[1], b_h[3]);
                }
            }
        }
    }

    float* dst = (by == 0) ? g_xw : outp;
    const float* bias = g_bc + by * 128;
#pragma unroll
    for (int mt = 0; mt < 2; mt++) {
        const int r0 = bm + warp_m * 32 + mt * 16 + (lane >> 2);
#pragma unroll
        for (int nt2 = 0; nt2 < 8; nt2++) {
            const int cc = warp_n * 64 + nt2 * 8 + (lane & 3) * 2;
            const float b0 = bias[cc], b1 = bias[cc + 1];
            if (r0 < M) {
                float2 v = make_float2(acc[mt][nt2][0] + b0, acc[mt][nt2][1] + b1);
                *(float2*)(dst + (size_t)r0 * HD + cc) = v;
            }
            if (r0 + 8 < M) {
                float2 v = make_float2(acc[mt][nt2][2] + b0, acc[mt][nt2][3] + b1);
                *(float2*)(dst + (size_t)(r0 + 8) * HD + cc) = v;
            }
        }
    }
}

// ---------------- attention logits (one warp per node) -------------------------
__global__ void __launch_bounds__(256)
logits_k(const float* __restrict__ x,
         const float* __restrict__ a1w, const float* __restrict__ a1b,
         const float* __restrict__ a2w, const float* __restrict__ a2b,
         int n)
{
    __shared__ float ws[8][K_DIM];
    for (int i = threadIdx.x; i < 4 * K_DIM; i += blockDim.x) {
        ws[i >> 8][i & 255]       = a1w[i];
        ws[4 + (i >> 8)][i & 255] = a2w[i];
    }
    __syncthreads();

    const int warp_id = (blockIdx.x * blockDim.x + threadIdx.x) >> 5;
    const int lane = threadIdx.x & 31;
    if (warp_id >= n) return;

    const float* xr = x + (size_t)warp_id * K_DIM;
    float xv[8];
#pragma unroll
    for (int j = 0; j < 8; j++) xv[j] = xr[lane + 32 * j];

#pragma unroll
    for (int h = 0; h < 8; h++) {
        float p = 0.f;
#pragma unroll
        for (int j = 0; j < 8; j++) p += xv[j] * ws[h][lane + 32 * j];
#pragma unroll
        for (int o = 16; o; o >>= 1) p += __shfl_xor_sync(0xffffffffu, p, o);
        if (lane == 0) {
            if (h < 4) g_s1[(size_t)warp_id * 4 + h]     = p + a1b[h];
            else       g_s2[(size_t)warp_id * 4 + h - 4] = p + a2b[h - 4];
        }
    }
}

// ---------------- CSR offsets ----------------------------------------------------
__global__ void offsets_k(const int* __restrict__ row, int n, int e)
{
    const int i = blockIdx.x * blockDim.x + threadIdx.x;
    if (i > n) return;
    int lo = 0, hi = e;
    while (lo < hi) {
        const int mid = (lo + hi) >> 1;
        if (row[mid] < i) lo = mid + 1; else hi = mid;
    }
    g_off[i] = lo;
}

// ---------------- segment softmax + aggregation: lane-parallel online ------------
__global__ void __launch_bounds__(256)
agg_k(const int* __restrict__ col, float* __restrict__ out, int n)
{
    const int warp_id = (blockIdx.x * blockDim.x + threadIdx.x) >> 5;
    const int lane = threadIdx.x & 31;
    if (warp_id >= n) return;

    const int e0 = g_off[warp_id];
    const int e1 = g_off[warp_id + 1];

    const float4 s14 = *(const float4*)(g_s1 + (size_t)warp_id * 4);  // broadcast

    float m0 = -INFINITY, m1 = -INFINITY, m2 = -INFINITY, m3 = -INFINITY;
    float sum0 = 0.f, sum1 = 0.f, sum2 = 0.f, sum3 = 0.f;   // per-lane partial
    float acc0 = 0.f, acc1 = 0.f, acc2 = 0.f, acc3 = 0.f;

    for (int blk = e0; blk < e1; blk += 32) {
        const int idx = blk + lane;
        const bool v = idx < e1;
        const int c_own = v ? col[idx] : 0;

        // per-lane logits for owned edge (full-MLP gather of s2)
        float a0 = -INFINITY, a1 = -INFINITY, a2 = -INFINITY, a3 = -INFINITY;
        if (v) {
            const float4 s2v = *(const float4*)(g_s2 + (size_t)c_own * 4);
            a0 = s14.x + s2v.x; a1 = s14.y + s2v.y;
            a2 = s14.z + s2v.z; a3 = s14.w + s2v.w;
        }

        // block max per head (butterfly)
        float b0 = a0, b1 = a1, b2 = a2, b3 = a3;
#pragma unroll
        for (int o = 16; o; o >>= 1) {
            b0 = fmaxf(b0, __shfl_xor_sync(0xffffffffu, b0, o));
            b1 = fmaxf(b1, __shfl_xor_sync(0xffffffffu, b1, o));
            b2 = fmaxf(b2, __shfl_xor_sync(0xffffffffu, b2, o));
            b3 = fmaxf(b3, __shfl_xor_sync(0xffffffffu, b3, o));
        }
        const float n0 = fmaxf(m0, b0), n1 = fmaxf(m1, b1);
        const float n2 = fmaxf(m2, b2), n3 = fmaxf(m3, b3);

        // rescale running state (r = exp(old - new); first block: exp(-inf)=0)
        const float r0 = __expf(m0 - n0), r1 = __expf(m1 - n1);
        const float r2 = __expf(m2 - n2), r3 = __expf(m3 - n3);
        m0 = n0; m1 = n1; m2 = n2; m3 = n3;
        acc0 *= r0; acc1 *= r1; acc2 *= r2; acc3 *= r3;
        sum0 *= r0; sum1 *= r1; sum2 *= r2; sum3 *= r3;

        // per-lane softmax numerators (invalid lanes: exp(-inf - m) = 0)
        const float p0 = __expf(a0 - m0), p1 = __expf(a1 - m1);
        const float p2 = __expf(a2 - m2), p3 = __expf(a3 - m3);
        sum0 += p0; sum1 += p1; sum2 += p2; sum3 += p3;

        // weighted gather of xw[col] (lane = feature index per head)
        const int nb = min(32, e1 - blk);
#pragma unroll 4
        for (int j = 0; j < nb; j++) {
            const int   c  = __shfl_sync(0xffffffffu, c_own, j);
            const float w0 = __shfl_sync(0xffffffffu, p0, j);
            const float w1 = __shfl_sync(0xffffffffu, p1, j);
            const float w2 = __shfl_sync(0xffffffffu, p2, j);
            const float w3 = __shfl_sync(0xffffffffu, p3, j);
            const float* xr = g_xw + (size_t)c * HD;
            acc0 = fmaf(w0, xr[lane],      acc0);
            acc1 = fmaf(w1, xr[32 + lane], acc1);
            acc2 = fmaf(w2, xr[64 + lane], acc2);
            acc3 = fmaf(w3, xr[96 + lane], acc3);
        }
    }

    // final per-head sum across lanes
#pragma unroll
    for (int o = 16; o; o >>= 1) {
        sum0 += __shfl_xor_sync(0xffffffffu, sum0, o);
        sum1 += __shfl_xor_sync(0xffffffffu, sum1, o);
        sum2 += __shfl_xor_sync(0xffffffffu, sum2, o);
        sum3 += __shfl_xor_sync(0xffffffffu, sum3, o);
    }
    const float i0 = 1.f / (sum0 + 1e-16f);
    const float i1 = 1.f / (sum1 + 1e-16f);
    const float i2 = 1.f / (sum2 + 1e-16f);
    const float i3 = 1.f / (sum3 + 1e-16f);

    float* o = out + (size_t)warp_id * HD;
    o[lane]      += acc0 * i0;
    o[32 + lane] += acc1 * i1;
    o[64 + lane] += acc2 * i2;
    o[96 + lane] += acc3 * i3;
}

// ---------------- launch ---------------------------------------------------------
extern "C" void kernel_launch(void* const* d_in, const int* in_sizes, int n_in,
                              void* d_out, int out_size)
{
    const float* x   = (const float*)d_in[0];
    const int*   row = (const int*)d_in[1];
    const int*   col = (const int*)d_in[2];
    const float* a1w = (const float*)d_in[3];
    const float* a1b = (const float*)d_in[4];
    const float* a2w = (const float*)d_in[5];
    const float* a2b = (const float*)d_in[6];
    const float* llw = (const float*)d_in[7];
    const float* llb = (const float*)d_in[8];
    const float* lrw = (const float*)d_in[9];
    const float* lrb = (const float*)d_in[10];

    const int n = in_sizes[0] / K_DIM;
    const int e = in_sizes[1];
    float* outp = (float*)d_out;

    wprep_k<<<256, 256>>>(llw, llb, lrw, lrb);
    offsets_k<<<(n + 1 + 255) / 256, 256>>>(row, n, e);
    logits_k<<<(n * 32 + 255) / 256, 256>>>(x, a1w, a1b, a2w, a2b, n);
    dim3 gg((n + 127) / 128, 2);
    gemm_mma_k<<<gg, 256>>>(x, outp, n);
    agg_k<<<(n * 32 + 255) / 256, 256>>>(col, outp, n);
}

// round 8
// speedup vs baseline: 1.8396x; 1.0179x over previous
#include <cuda_runtime.h>
#include <cuda_bf16.h>
#include <cuda_fp16.h>
#include <math.h>
#include <stdint.h>

#define K_DIM 256
#define HD 128
#define MAX_N 100000
#define MAX_E 1600000

// ---------------- scratch (static device arrays; no allocation) ----------------
__device__ __half g_xwh[(size_t)MAX_N * HD];      // x @ lin_l^T + b (fp16) [N,128]
__device__ float g_s1[(size_t)MAX_N * 4];         // a1 logits per node [N,4]
__device__ float g_s2[(size_t)MAX_N * 4];         // a2 logits per node [N,4]
__device__ __nv_bfloat16 g_bh[272 * 256];         // W_cat hi [264 used][256 k]
__device__ __nv_bfloat16 g_bl[272 * 256];         // W_cat lo
__device__ float g_bc[272];                       // bias cat (264 used)

// ---------------- PTX helpers ---------------------------------------------------
__device__ __forceinline__ uint32_t smem_u32(const void* p) {
    uint32_t a;
    asm("{ .reg .u64 t; cvta.to.shared.u64 t, %1; cvt.u32.u64 %0, t; }" : "=r"(a) : "l"(p));
    return a;
}
__device__ __forceinline__ void ldsm4(uint32_t* r, uint32_t addr) {
    asm volatile("ldmatrix.sync.aligned.m8n8.x4.shared.b16 {%0,%1,%2,%3}, [%4];"
                 : "=r"(r[0]), "=r"(r[1]), "=r"(r[2]), "=r"(r[3]) : "r"(addr));
}
__device__ __forceinline__ void ldsm2(uint32_t* r, uint32_t addr) {
    asm volatile("ldmatrix.sync.aligned.m8n8.x2.shared.b16 {%0,%1}, [%2];"
                 : "=r"(r[0]), "=r"(r[1]) : "r"(addr));
}
__device__ __forceinline__ void mma_bf16(float* c, const uint32_t* a, uint32_t b0, uint32_t b1) {
    asm volatile(
        "mma.sync.aligned.m16n8k16.row.col.f32.bf16.bf16.f32 "
        "{%0,%1,%2,%3}, {%4,%5,%6,%7}, {%8,%9}, {%0,%1,%2,%3};"
        : "+f"(c[0]), "+f"(c[1]), "+f"(c[2]), "+f"(c[3])
        : "r"(a[0]), "r"(a[1]), "r"(a[2]), "r"(a[3]), "r"(b0), "r"(b1));
}

// ---------------- weight prep: fp32 -> bf16 hi/lo, concat [lin_l|lin_r|a1|a2] ---
__global__ void wprep_k(const float* __restrict__ llw, const float* __restrict__ llb,
                        const float* __restrict__ lrw, const float* __restrict__ lrb,
                        const float* __restrict__ a1w, const float* __restrict__ a1b,
                        const float* __restrict__ a2w, const float* __restrict__ a2b)
{
    const int idx = blockIdx.x * blockDim.x + threadIdx.x;   // 0..67583
    const int n = idx >> 8, k = idx & 255;
    float v;
    if      (n < 128) v = llw[n * 256 + k];
    else if (n < 256) v = lrw[(n - 128) * 256 + k];
    else if (n < 260) v = a1w[(n - 256) * 256 + k];
    else              v = a2w[(n - 260) * 256 + k];
    const __nv_bfloat16 hi = __float2bfloat16(v);
    const __nv_bfloat16 lo = __float2bfloat16(v - __bfloat162float(hi));
    g_bh[idx] = hi;
    g_bl[idx] = lo;
    if (idx < 264) {
        float b;
        if      (idx < 128) b = llb[idx];
        else if (idx < 256) b = lrb[idx - 128];
        else if (idx < 260) b = a1b[idx - 256];
        else                b = a2b[idx - 260];
        g_bc[idx] = b;
    }
}

// ---------------- HMMA bf16-split GEMM + fused attention logits -----------------
// grid = (ceil(M/128), 2). y=0 -> g_xwh (fp16) + logits s1/s2; y=1 -> out (lin_r).
#define LDS_STRIDE 40

__global__ void __launch_bounds__(256, 2)
gemm_mma_k(const float* __restrict__ A, float* __restrict__ outp, int M)
{
    __shared__ __align__(16) __nv_bfloat16 Ah[128 * LDS_STRIDE];
    __shared__ __align__(16) __nv_bfloat16 Al[128 * LDS_STRIDE];
    __shared__ __align__(16) __nv_bfloat16 Bh[128 * LDS_STRIDE];
    __shared__ __align__(16) __nv_bfloat16 Bl[128 * LDS_STRIDE];
    __shared__ __align__(16) __nv_bfloat16 Bxh[8 * LDS_STRIDE];
    __shared__ __align__(16) __nv_bfloat16 Bxl[8 * LDS_STRIDE];
    __shared__ float s_acc[128 * 9];   // logits accumulator [row][8 cols], pad 9

    const int tid = threadIdx.x;
    const int wid = tid >> 5;
    const int lane = tid & 31;
    const int bm = blockIdx.x * 128;
    const int by = blockIdx.y;
    const int warp_m = wid & 3;
    const int warp_n = wid >> 2;

    // zero logits accumulator
    for (int i = tid; i < 128 * 9; i += 256) s_acc[i] = 0.f;

    float acc[2][8][4];
#pragma unroll
    for (int i = 0; i < 2; i++)
#pragma unroll
        for (int j = 0; j < 8; j++)
#pragma unroll
            for (int q = 0; q < 4; q++) acc[i][j][q] = 0.f;

    const int lrow = tid >> 1;
    const int lhalf = tid & 1;
    const bool avalid = (bm + lrow) < M;
    const float* ag = A + (size_t)(bm + lrow) * K_DIM + lhalf * 16;
    const __nv_bfloat16* bgh = g_bh + (size_t)(by * 128 + lrow) * 256 + lhalf * 16;
    const __nv_bfloat16* bgl = g_bl + (size_t)(by * 128 + lrow) * 256 + lhalf * 16;
    // extra logits weights (rows 256..263), loaded by threads 0..15
    const __nv_bfloat16* bgxh = g_bh + (size_t)(256 + (tid >> 1)) * 256 + lhalf * 16;
    const __nv_bfloat16* bgxl = g_bl + (size_t)(256 + (tid >> 1)) * 256 + lhalf * 16;

    const uint32_t ah_s = smem_u32(Ah);
    const uint32_t al_s = smem_u32(Al);
    const uint32_t bh_s = smem_u32(Bh);
    const uint32_t bl_s = smem_u32(Bl);
    const uint32_t bxh_s = smem_u32(Bxh);
    const uint32_t bxl_s = smem_u32(Bxl);

    char* ah_p = (char*)Ah; char* al_p = (char*)Al;
    char* bh_p = (char*)Bh; char* bl_p = (char*)Bl;
    char* bxh_p = (char*)Bxh; char* bxl_p = (char*)Bxl;
    const uint32_t st_off = lrow * (LDS_STRIDE * 2) + lhalf * 32;

    for (int c = 0; c < 8; c++) {
        if (c) __syncthreads();

#pragma unroll
        for (int q = 0; q < 4; q++) {
            float4 f = avalid ? *(const float4*)(ag + c * 32 + q * 4) : make_float4(0, 0, 0, 0);
            __nv_bfloat162 h0 = __floats2bfloat162_rn(f.x, f.y);
            __nv_bfloat162 h1 = __floats2bfloat162_rn(f.z, f.w);
            float2 fh0 = __bfloat1622float2(h0), fh1 = __bfloat1622float2(h1);
            __nv_bfloat162 l0 = __floats2bfloat162_rn(f.x - fh0.x, f.y - fh0.y);
            __nv_bfloat162 l1 = __floats2bfloat162_rn(f.z - fh1.x, f.w - fh1.y);
            uint2 hv, lv;
            hv.x = *(uint32_t*)&h0; hv.y = *(uint32_t*)&h1;
            lv.x = *(uint32_t*)&l0; lv.y = *(uint32_t*)&l1;
            *(uint2*)(ah_p + st_off + q * 8) = hv;
            *(uint2*)(al_p + st_off + q * 8) = lv;
        }
        {
            const uint4* sh = (const uint4*)(bgh + c * 32);
            const uint4* sl = (const uint4*)(bgl + c * 32);
            *(uint4*)(bh_p + st_off)      = sh[0];
            *(uint4*)(bh_p + st_off + 16) = sh[1];
            *(uint4*)(bl_p + st_off)      = sl[0];
            *(uint4*)(bl_p + st_off + 16) = sl[1];
        }
        if (by == 0 && tid < 16) {
            const uint4* sh = (const uint4*)(bgxh + c * 32);
            const uint4* sl = (const uint4*)(bgxl + c * 32);
            *(uint4*)(bxh_p + st_off)      = sh[0];
            *(uint4*)(bxh_p + st_off + 16) = sh[1];
            *(uint4*)(bxl_p + st_off)      = sl[0];
            *(uint4*)(bxl_p + st_off + 16) = sl[1];
        }
        __syncthreads();

        float cx[2][4] = {{0.f, 0.f, 0.f, 0.f}, {0.f, 0.f, 0.f, 0.f}};

#pragma unroll
        for (int ks = 0; ks < 2; ks++) {
            const uint32_t kb = ks * 32 + (lane >> 4) * 16;
            uint32_t a_h[2][4], a_l[2][4];
#pragma unroll
            for (int mt = 0; mt < 2; mt++) {
                const uint32_t ro = (warp_m * 32 + mt * 16 + (lane & 15)) * (LDS_STRIDE * 2) + kb;
                ldsm4(a_h[mt], ah_s + ro);
                ldsm4(a_l[mt], al_s + ro);
            }
#pragma unroll
            for (int nt = 0; nt < 4; nt++) {
                const uint32_t ro = (warp_n * 64 + nt * 16 + (lane & 15)) * (LDS_STRIDE * 2) + kb;
                uint32_t b_h[4], b_l[4];
                ldsm4(b_h, bh_s + ro);
                ldsm4(b_l, bl_s + ro);
#pragma unroll
                for (int mt = 0; mt < 2; mt++) {
                    mma_bf16(acc[mt][nt * 2],     a_h[mt], b_h[0], b_h[2]);
                    mma_bf16(acc[mt][nt * 2 + 1], a_h[mt], b_h[1], b_h[3]);
                    mma_bf16(acc[mt][nt * 2],     a_h[mt], b_l[0], b_l[2]);
                    mma_bf16(acc[mt][nt * 2 + 1], a_h[mt], b_l[1], b_l[3]);
                    mma_bf16(acc[mt][nt * 2],     a_l[mt], b_h[0], b_h[2]);
                    mma_bf16(acc[mt][nt * 2 + 1], a_l[mt], b_h[1], b_h[3]);
                }
            }
            // fused logits MMA: 8 extra cols, warp_n==0 warps of by==0
            if (by == 0 && warp_n == 0) {
                const int la = lane & 15;
                const uint32_t rox = (la & 7) * (LDS_STRIDE * 2) + ((la >> 3) & 1) * 16 + ks * 32;
                uint32_t bx_h[2], bx_l[2];
                ldsm2(bx_h, bxh_s + rox);
                ldsm2(bx_l, bxl_s + rox);
#pragma unroll
                for (int mt = 0; mt < 2; mt++) {
                    mma_bf16(cx[mt], a_h[mt], bx_h[0], bx_h[1]);
                    mma_bf16(cx[mt], a_h[mt], bx_l[0], bx_l[1]);
                    mma_bf16(cx[mt], a_l[mt], bx_h[0], bx_h[1]);
                }
            }
        }
        if (by == 0 && warp_n == 0) {
#pragma unroll
            for (int mt = 0; mt < 2; mt++) {
                const int r = warp_m * 32 + mt * 16 + (lane >> 2);
                const int cc = (lane & 3) * 2;
                s_acc[r * 9 + cc]           += cx[mt][0];
                s_acc[r * 9 + cc + 1]       += cx[mt][1];
                s_acc[(r + 8) * 9 + cc]     += cx[mt][2];
                s_acc[(r + 8) * 9 + cc + 1] += cx[mt][3];
            }
        }
    }

    // ---- main epilogue ----
    if (by == 0) {
        // xw in fp16
#pragma unroll
        for (int mt = 0; mt < 2; mt++) {
            const int r0 = bm + warp_m * 32 + mt * 16 + (lane >> 2);
#pragma unroll
            for (int nt2 = 0; nt2 < 8; nt2++) {
                const int cc = warp_n * 64 + nt2 * 8 + (lane & 3) * 2;
                const float b0 = g_bc[cc], b1 = g_bc[cc + 1];
                if (r0 < M)
                    g_xwh[((size_t)r0 * HD + cc) >> 1 << 1], // no-op keep layout clear
                    *(__half2*)(g_xwh + (size_t)r0 * HD + cc) =
                        __floats2half2_rn(acc[mt][nt2][0] + b0, acc[mt][nt2][1] + b1);
                if (r0 + 8 < M)
                    *(__half2*)(g_xwh + (size_t)(r0 + 8) * HD + cc) =
                        __floats2half2_rn(acc[mt][nt2][2] + b0, acc[mt][nt2][3] + b1);
            }
        }
        // logits epilogue
        __syncthreads();
#pragma unroll
        for (int it = 0; it < 4; it++) {
            const int idx = tid + it * 256;            // 0..1023
            const int r = idx >> 3, cc = idx & 7;
            const int gr = bm + r;
            if (gr < M) {
                const float v = s_acc[r * 9 + cc] + g_bc[256 + cc];
                if (cc < 4) g_s1[(size_t)gr * 4 + cc] = v;
                else        g_s2[(size_t)gr * 4 + cc - 4] = v;
            }
        }
    } else {
        const float* bias = g_bc + 128;
#pragma unroll
        for (int mt = 0; mt < 2; mt++) {
            const int r0 = bm + warp_m * 32 + mt * 16 + (lane >> 2);
#pragma unroll
            for (int nt2 = 0; nt2 < 8; nt2++) {
                const int cc = warp_n * 64 + nt2 * 8 + (lane & 3) * 2;
                const float b0 = bias[cc], b1 = bias[cc + 1];
                if (r0 < M)
                    *(float2*)(outp + (size_t)r0 * HD + cc) =
                        make_float2(acc[mt][nt2][0] + b0, acc[mt][nt2][1] + b1);
                if (r0 + 8 < M)
                    *(float2*)(outp + (size_t)(r0 + 8) * HD + cc) =
                        make_float2(acc[mt][nt2][2] + b0, acc[mt][nt2][3] + b1);
            }
        }
    }
}

// ---------------- segment softmax + aggregation (fused CSR search, fp16 gather) -
__global__ void __launch_bounds__(256)
agg_k(const int* __restrict__ row, const int* __restrict__ col,
      float* __restrict__ out, int n, int e)
{
    const int warp_id = (blockIdx.x * blockDim.x + threadIdx.x) >> 5;
    const int lane = threadIdx.x & 31;
    if (warp_id >= n) return;

    // fused CSR boundary search (lanes 0/1 compute, all lanes converged)
    {
        const int target = warp_id + (lane & 1);
        int lo = 0, hi = e;
        while (lo < hi) {
            const int mid = (lo + hi) >> 1;
            if (row[mid] < target) lo = mid + 1; else hi = mid;
        }
        const int r0 = __shfl_sync(0xffffffffu, lo, 0);
        const int r1 = __shfl_sync(0xffffffffu, lo, 1);
        // reuse as e0/e1 below
        if (r0 >= r1) {   // isolated node: out already holds lin_r part
            return;
        }
        // fallthrough with e0=r0, e1=r1 via variables
        const int e0 = r0, e1 = r1;

        const float4 s14 = *(const float4*)(g_s1 + (size_t)warp_id * 4);

        float m0 = -INFINITY, m1 = -INFINITY, m2 = -INFINITY, m3 = -INFINITY;
        float sum0 = 0.f, sum1 = 0.f, sum2 = 0.f, sum3 = 0.f;
        float accA0 = 0.f, accA1 = 0.f, accB0 = 0.f, accB1 = 0.f;
        const bool hiHalf = lane >= 16;

        for (int blk = e0; blk < e1; blk += 32) {
            const int idx = blk + lane;
            const bool v = idx < e1;
            const int c_own = v ? col[idx] : 0;

            float a0 = -INFINITY, a1 = -INFINITY, a2 = -INFINITY, a3 = -INFINITY;
            if (v) {
                const float4 s2v = *(const float4*)(g_s2 + (size_t)c_own * 4);
                a0 = s14.x + s2v.x; a1 = s14.y + s2v.y;
                a2 = s14.z + s2v.z; a3 = s14.w + s2v.w;
            }

            float b0 = a0, b1 = a1, b2 = a2, b3 = a3;
#pragma unroll
            for (int o = 16; o; o >>= 1) {
                b0 = fmaxf(b0, __shfl_xor_sync(0xffffffffu, b0, o));
                b1 = fmaxf(b1, __shfl_xor_sync(0xffffffffu, b1, o));
                b2 = fmaxf(b2, __shfl_xor_sync(0xffffffffu, b2, o));
                b3 = fmaxf(b3, __shfl_xor_sync(0xffffffffu, b3, o));
            }
            const float n0 = fmaxf(m0, b0), n1 = fmaxf(m1, b1);
            const float n2 = fmaxf(m2, b2), n3 = fmaxf(m3, b3);

            const float r0s = __expf(m0 - n0), r1s = __expf(m1 - n1);
            const float r2s = __expf(m2 - n2), r3s = __expf(m3 - n3);
            m0 = n0; m1 = n1; m2 = n2; m3 = n3;
            const float rA = hiHalf ? r1s : r0s;
            const float rB = hiHalf ? r3s : r2s;
            accA0 *= rA; accA1 *= rA; accB0 *= rB; accB1 *= rB;
            sum0 *= r0s; sum1 *= r1s; sum2 *= r2s; sum3 *= r3s;

            const float p0 = __expf(a0 - m0), p1 = __expf(a1 - m1);
            const float p2 = __expf(a2 - m2), p3 = __expf(a3 - m3);
            sum0 += p0; sum1 += p1; sum2 += p2; sum3 += p3;

            const int nb = min(32, e1 - blk);
#pragma unroll 4
            for (int j = 0; j < nb; j++) {
                const int   c  = __shfl_sync(0xffffffffu, c_own, j);
                const float w0 = __shfl_sync(0xffffffffu, p0, j);
                const float w1 = __shfl_sync(0xffffffffu, p1, j);
                const float w2 = __shfl_sync(0xffffffffu, p2, j);
                const float w3 = __shfl_sync(0xffffffffu, p3, j);
                const __half2* xr = (const __half2*)(g_xwh + (size_t)c * HD);
                const float2 fa = __half22float2(xr[lane]);
                const float2 fb = __half22float2(xr[32 + lane]);
                const float wA = hiHalf ? w1 : w0;
                const float wB = hiHalf ? w3 : w2;
                accA0 = fmaf(wA, fa.x, accA0);
                accA1 = fmaf(wA, fa.y, accA1);
                accB0 = fmaf(wB, fb.x, accB0);
                accB1 = fmaf(wB, fb.y, accB1);
            }
        }

#pragma unroll
        for (int o = 16; o; o >>= 1) {
            sum0 += __shfl_xor_sync(0xffffffffu, sum0, o);
            sum1 += __shfl_xor_sync(0xffffffffu, sum1, o);
            sum2 += __shfl_xor_sync(0xffffffffu, sum2, o);
            sum3 += __shfl_xor_sync(0xffffffffu, sum3, o);
        }
        const float i0 = 1.f / (sum0 + 1e-16f);
        const float i1 = 1.f / (sum1 + 1e-16f);
        const float i2 = 1.f / (sum2 + 1e-16f);
        const float i3 = 1.f / (sum3 + 1e-16f);
        const float iA = hiHalf ? i1 : i0;
        const float iB = hiHalf ? i3 : i2;

        float* o = out + (size_t)warp_id * HD;
        float2 cA = *(float2*)(o + 2 * lane);
        float2 cB = *(float2*)(o + 64 + 2 * lane);
        cA.x += accA0 * iA; cA.y += accA1 * iA;
        cB.x += accB0 * iB; cB.y += accB1 * iB;
        *(float2*)(o + 2 * lane)      = cA;
        *(float2*)(o + 64 + 2 * lane) = cB;
    }
}

// ---------------- launch ---------------------------------------------------------
extern "C" void kernel_launch(void* const* d_in, const int* in_sizes, int n_in,
                              void* d_out, int out_size)
{
    const float* x   = (const float*)d_in[0];
    const int*   row = (const int*)d_in[1];
    const int*   col = (const int*)d_in[2];
    const float* a1w = (const float*)d_in[3];
    const float* a1b = (const float*)d_in[4];
    const float* a2w = (const float*)d_in[5];
    const float* a2b = (const float*)d_in[6];
    const float* llw = (const float*)d_in[7];
    const float* llb = (const float*)d_in[8];
    const float* lrw = (const float*)d_in[9];
    const float* lrb = (const float*)d_in[10];

    const int n = in_sizes[0] / K_DIM;
    const int e = in_sizes[1];
    float* outp = (float*)d_out;

    wprep_k<<<264, 256>>>(llw, llb, lrw, lrb, a1w, a1b, a2w, a2b);
    dim3 gg((n + 127) / 128, 2);
    gemm_mma_k<<<gg, 256>>>(x, outp, n);
    agg_k<<<(n * 32 + 255) / 256, 256>>>(row, col, outp, n, e);
}

// round 9
// speedup vs baseline: 2.1434x; 1.1651x over previous
#include <cuda_runtime.h>
#include <cuda_bf16.h>
#include <cuda_fp16.h>
#include <math.h>
#include <stdint.h>

#define K_DIM 256
#define HD 128
#define MAX_N 100000
#define MAX_E 1600000

// ---------------- scratch (static device arrays; no allocation) ----------------
__device__ __half g_xwh[(size_t)MAX_N * HD];      // x @ lin_l^T + b (fp16) [N,128]
__device__ float g_s1[(size_t)MAX_N * 4];         // a1 logits per node [N,4]
__device__ float g_s2[(size_t)MAX_N * 4];         // a2 logits per node [N,4]
__device__ int   g_off[MAX_N + 1];                // CSR offsets
__device__ __nv_bfloat16 g_bh[272 * 256];         // W_cat hi [264 used][256 k]
__device__ __nv_bfloat16 g_bl[272 * 256];         // W_cat lo
__device__ float g_bc[272];                       // bias cat (264 used)

// ---------------- PTX helpers ---------------------------------------------------
__device__ __forceinline__ uint32_t smem_u32(const void* p) {
    uint32_t a;
    asm("{ .reg .u64 t; cvta.to.shared.u64 t, %1; cvt.u32.u64 %0, t; }" : "=r"(a) : "l"(p));
    return a;
}
__device__ __forceinline__ void ldsm4(uint32_t* r, uint32_t addr) {
    asm volatile("ldmatrix.sync.aligned.m8n8.x4.shared.b16 {%0,%1,%2,%3}, [%4];"
                 : "=r"(r[0]), "=r"(r[1]), "=r"(r[2]), "=r"(r[3]) : "r"(addr));
}
__device__ __forceinline__ void ldsm2(uint32_t* r, uint32_t addr) {
    asm volatile("ldmatrix.sync.aligned.m8n8.x2.shared.b16 {%0,%1}, [%2];"
                 : "=r"(r[0]), "=r"(r[1]) : "r"(addr));
}
__device__ __forceinline__ void mma_bf16(float* c, const uint32_t* a, uint32_t b0, uint32_t b1) {
    asm volatile(
        "mma.sync.aligned.m16n8k16.row.col.f32.bf16.bf16.f32 "
        "{%0,%1,%2,%3}, {%4,%5,%6,%7}, {%8,%9}, {%0,%1,%2,%3};"
        : "+f"(c[0]), "+f"(c[1]), "+f"(c[2]), "+f"(c[3])
        : "r"(a[0]), "r"(a[1]), "r"(a[2]), "r"(a[3]), "r"(b0), "r"(b1));
}

// ---------------- weight prep: fp32 -> bf16 hi/lo, concat [lin_l|lin_r|a1|a2] ---
__global__ void wprep_k(const float* __restrict__ llw, const float* __restrict__ llb,
                        const float* __restrict__ lrw, const float* __restrict__ lrb,
                        const float* __restrict__ a1w, const float* __restrict__ a1b,
                        const float* __restrict__ a2w, const float* __restrict__ a2b)
{
    const int idx = blockIdx.x * blockDim.x + threadIdx.x;   // 0..67583
    const int n = idx >> 8, k = idx & 255;
    float v;
    if      (n < 128) v = llw[n * 256 + k];
    else if (n < 256) v = lrw[(n - 128) * 256 + k];
    else if (n < 260) v = a1w[(n - 256) * 256 + k];
    else              v = a2w[(n - 260) * 256 + k];
    const __nv_bfloat16 hi = __float2bfloat16(v);
    const __nv_bfloat16 lo = __float2bfloat16(v - __bfloat162float(hi));
    g_bh[idx] = hi;
    g_bl[idx] = lo;
    if (idx < 264) {
        float b;
        if      (idx < 128) b = llb[idx];
        else if (idx < 256) b = lrb[idx - 128];
        else if (idx < 260) b = a1b[idx - 256];
        else                b = a2b[idx - 260];
        g_bc[idx] = b;
    }
}

// ---------------- HMMA bf16-split GEMM + fused attention logits -----------------
// grid = (ceil(M/128), 2). y=0 -> g_xwh (fp16) + logits s1/s2; y=1 -> out (lin_r).
#define LDS_STRIDE 40

__global__ void __launch_bounds__(256, 2)
gemm_mma_k(const float* __restrict__ A, float* __restrict__ outp, int M)
{
    __shared__ __align__(16) __nv_bfloat16 Ah[128 * LDS_STRIDE];
    __shared__ __align__(16) __nv_bfloat16 Al[128 * LDS_STRIDE];
    __shared__ __align__(16) __nv_bfloat16 Bh[128 * LDS_STRIDE];
    __shared__ __align__(16) __nv_bfloat16 Bl[128 * LDS_STRIDE];
    __shared__ __align__(16) __nv_bfloat16 Bxh[8 * LDS_STRIDE];
    __shared__ __align__(16) __nv_bfloat16 Bxl[8 * LDS_STRIDE];
    __shared__ float s_acc[128 * 9];   // logits accumulator [row][8 cols], pad 9

    const int tid = threadIdx.x;
    const int wid = tid >> 5;
    const int lane = tid & 31;
    const int bm = blockIdx.x * 128;
    const int by = blockIdx.y;
    const int warp_m = wid & 3;
    const int warp_n = wid >> 2;

    for (int i = tid; i < 128 * 9; i += 256) s_acc[i] = 0.f;

    float acc[2][8][4];
#pragma unroll
    for (int i = 0; i < 2; i++)
#pragma unroll
        for (int j = 0; j < 8; j++)
#pragma unroll
            for (int q = 0; q < 4; q++) acc[i][j][q] = 0.f;

    const int lrow = tid >> 1;
    const int lhalf = tid & 1;
    const bool avalid = (bm + lrow) < M;
    const float* ag = A + (size_t)(bm + lrow) * K_DIM + lhalf * 16;
    const __nv_bfloat16* bgh = g_bh + (size_t)(by * 128 + lrow) * 256 + lhalf * 16;
    const __nv_bfloat16* bgl = g_bl + (size_t)(by * 128 + lrow) * 256 + lhalf * 16;
    const __nv_bfloat16* bgxh = g_bh + (size_t)(256 + (tid >> 1)) * 256 + lhalf * 16;
    const __nv_bfloat16* bgxl = g_bl + (size_t)(256 + (tid >> 1)) * 256 + lhalf * 16;

    const uint32_t ah_s = smem_u32(Ah);
    const uint32_t al_s = smem_u32(Al);
    const uint32_t bh_s = smem_u32(Bh);
    const uint32_t bl_s = smem_u32(Bl);
    const uint32_t bxh_s = smem_u32(Bxh);
    const uint32_t bxl_s = smem_u32(Bxl);

    char* ah_p = (char*)Ah; char* al_p = (char*)Al;
    char* bh_p = (char*)Bh; char* bl_p = (char*)Bl;
    char* bxh_p = (char*)Bxh; char* bxl_p = (char*)Bxl;
    const uint32_t st_off = lrow * (LDS_STRIDE * 2) + lhalf * 32;

    for (int c = 0; c < 8; c++) {
        if (c) __syncthreads();

#pragma unroll
        for (int q = 0; q < 4; q++) {
            float4 f = avalid ? *(const float4*)(ag + c * 32 + q * 4) : make_float4(0, 0, 0, 0);
            __nv_bfloat162 h0 = __floats2bfloat162_rn(f.x, f.y);
            __nv_bfloat162 h1 = __floats2bfloat162_rn(f.z, f.w);
            float2 fh0 = __bfloat1622float2(h0), fh1 = __bfloat1622float2(h1);
            __nv_bfloat162 l0 = __floats2bfloat162_rn(f.x - fh0.x, f.y - fh0.y);
            __nv_bfloat162 l1 = __floats2bfloat162_rn(f.z - fh1.x, f.w - fh1.y);
            uint2 hv, lv;
            hv.x = *(uint32_t*)&h0; hv.y = *(uint32_t*)&h1;
            lv.x = *(uint32_t*)&l0; lv.y = *(uint32_t*)&l1;
            *(uint2*)(ah_p + st_off + q * 8) = hv;
            *(uint2*)(al_p + st_off + q * 8) = lv;
        }
        {
            const uint4* sh = (const uint4*)(bgh + c * 32);
            const uint4* sl = (const uint4*)(bgl + c * 32);
            *(uint4*)(bh_p + st_off)      = sh[0];
            *(uint4*)(bh_p + st_off + 16) = sh[1];
            *(uint4*)(bl_p + st_off)      = sl[0];
            *(uint4*)(bl_p + st_off + 16) = sl[1];
        }
        if (by == 0 && tid < 16) {
            const uint4* sh = (const uint4*)(bgxh + c * 32);
            const uint4* sl = (const uint4*)(bgxl + c * 32);
            *(uint4*)(bxh_p + st_off)      = sh[0];
            *(uint4*)(bxh_p + st_off + 16) = sh[1];
            *(uint4*)(bxl_p + st_off)      = sl[0];
            *(uint4*)(bxl_p + st_off + 16) = sl[1];
        }
        __syncthreads();

        float cx[2][4] = {{0.f, 0.f, 0.f, 0.f}, {0.f, 0.f, 0.f, 0.f}};

#pragma unroll
        for (int ks = 0; ks < 2; ks++) {
            const uint32_t kb = ks * 32 + (lane >> 4) * 16;
            uint32_t a_h[2][4], a_l[2][4];
#pragma unroll
            for (int mt = 0; mt < 2; mt++) {
                const uint32_t ro = (warp_m * 32 + mt * 16 + (lane & 15)) * (LDS_STRIDE * 2) + kb;
                ldsm4(a_h[mt], ah_s + ro);
                ldsm4(a_l[mt], al_s + ro);
            }
#pragma unroll
            for (int nt = 0; nt < 4; nt++) {
                const uint32_t ro = (warp_n * 64 + nt * 16 + (lane & 15)) * (LDS_STRIDE * 2) + kb;
                uint32_t b_h[4], b_l[4];
                ldsm4(b_h, bh_s + ro);
                ldsm4(b_l, bl_s + ro);
#pragma unroll
                for (int mt = 0; mt < 2; mt++) {
                    mma_bf16(acc[mt][nt * 2],     a_h[mt], b_h[0], b_h[2]);
                    mma_bf16(acc[mt][nt * 2 + 1], a_h[mt], b_h[1], b_h[3]);
                    mma_bf16(acc[mt][nt * 2],     a_h[mt], b_l[0], b_l[2]);
                    mma_bf16(acc[mt][nt * 2 + 1], a_h[mt], b_l[1], b_l[3]);
                    mma_bf16(acc[mt][nt * 2],     a_l[mt], b_h[0], b_h[2]);
                    mma_bf16(acc[mt][nt * 2 + 1], a_l[mt], b_h[1], b_h[3]);
                }
            }
            if (by == 0 && warp_n == 0) {
                const int la = lane & 15;
                const uint32_t rox = (la & 7) * (LDS_STRIDE * 2) + ((la >> 3) & 1) * 16 + ks * 32;
                uint32_t bx_h[2], bx_l[2];
                ldsm2(bx_h, bxh_s + rox);
                ldsm2(bx_l, bxl_s + rox);
#pragma unroll
                for (int mt = 0; mt < 2; mt++) {
                    mma_bf16(cx[mt], a_h[mt], bx_h[0], bx_h[1]);
                    mma_bf16(cx[mt], a_h[mt], bx_l[0], bx_l[1]);
                    mma_bf16(cx[mt], a_l[mt], bx_h[0], bx_h[1]);
                }
            }
        }
        if (by == 0 && warp_n == 0) {
#pragma unroll
            for (int mt = 0; mt < 2; mt++) {
                const int r = warp_m * 32 + mt * 16 + (lane >> 2);
                const int cc = (lane & 3) * 2;
                s_acc[r * 9 + cc]           += cx[mt][0];
                s_acc[r * 9 + cc + 1]       += cx[mt][1];
                s_acc[(r + 8) * 9 + cc]     += cx[mt][2];
                s_acc[(r + 8) * 9 + cc + 1] += cx[mt][3];
            }
        }
    }

    if (by == 0) {
#pragma unroll
        for (int mt = 0; mt < 2; mt++) {
            const int r0 = bm + warp_m * 32 + mt * 16 + (lane >> 2);
#pragma unroll
            for (int nt2 = 0; nt2 < 8; nt2++) {
                const int cc = warp_n * 64 + nt2 * 8 + (lane & 3) * 2;
                const float b0 = g_bc[cc], b1 = g_bc[cc + 1];
                if (r0 < M)
                    *(__half2*)(g_xwh + (size_t)r0 * HD + cc) =
                        __floats2half2_rn(acc[mt][nt2][0] + b0, acc[mt][nt2][1] + b1);
                if (r0 + 8 < M)
                    *(__half2*)(g_xwh + (size_t)(r0 + 8) * HD + cc) =
                        __floats2half2_rn(acc[mt][nt2][2] + b0, acc[mt][nt2][3] + b1);
            }
        }
        __syncthreads();
#pragma unroll
        for (int it = 0; it < 4; it++) {
            const int idx = tid + it * 256;
            const int r = idx >> 3, cc = idx & 7;
            const int gr = bm + r;
            if (gr < M) {
                const float v = s_acc[r * 9 + cc] + g_bc[256 + cc];
                if (cc < 4) g_s1[(size_t)gr * 4 + cc] = v;
                else        g_s2[(size_t)gr * 4 + cc - 4] = v;
            }
        }
    } else {
        const float* bias = g_bc + 128;
#pragma unroll
        for (int mt = 0; mt < 2; mt++) {
            const int r0 = bm + warp_m * 32 + mt * 16 + (lane >> 2);
#pragma unroll
            for (int nt2 = 0; nt2 < 8; nt2++) {
                const int cc = warp_n * 64 + nt2 * 8 + (lane & 3) * 2;
                const float b0 = bias[cc], b1 = bias[cc + 1];
                if (r0 < M)
                    *(float2*)(outp + (size_t)r0 * HD + cc) =
                        make_float2(acc[mt][nt2][0] + b0, acc[mt][nt2][1] + b1);
                if (r0 + 8 < M)
                    *(float2*)(outp + (size_t)(r0 + 8) * HD + cc) =
                        make_float2(acc[mt][nt2][2] + b0, acc[mt][nt2][3] + b1);
            }
        }
    }
}

// ---------------- CSR offsets (standalone, throughput-style) --------------------
__global__ void offsets_k(const int* __restrict__ row, int n, int e)
{
    const int i = blockIdx.x * blockDim.x + threadIdx.x;
    if (i > n) return;
    int lo = 0, hi = e;
    while (lo < hi) {
        const int mid = (lo + hi) >> 1;
        if (row[mid] < i) lo = mid + 1; else hi = mid;
    }
    g_off[i] = lo;
}

// ---------------- segment softmax + aggregation (fp16 gather, g_off) ------------
__global__ void __launch_bounds__(256)
agg_k(const int* __restrict__ col, float* __restrict__ out, int n)
{
    const int warp_id = (blockIdx.x * blockDim.x + threadIdx.x) >> 5;
    const int lane = threadIdx.x & 31;
    if (warp_id >= n) return;

    const int e0 = g_off[warp_id];
    const int e1 = g_off[warp_id + 1];
    if (e0 >= e1) return;   // isolated node: out already holds lin_r part

    const float4 s14 = *(const float4*)(g_s1 + (size_t)warp_id * 4);

    float m0 = -INFINITY, m1 = -INFINITY, m2 = -INFINITY, m3 = -INFINITY;
    float sum0 = 0.f, sum1 = 0.f, sum2 = 0.f, sum3 = 0.f;
    float accA0 = 0.f, accA1 = 0.f, accB0 = 0.f, accB1 = 0.f;
    const bool hiHalf = lane >= 16;

    for (int blk = e0; blk < e1; blk += 32) {
        const int idx = blk + lane;
        const bool v = idx < e1;
        const int c_own = v ? col[idx] : 0;

        float a0 = -INFINITY, a1 = -INFINITY, a2 = -INFINITY, a3 = -INFINITY;
        if (v) {
            const float4 s2v = *(const float4*)(g_s2 + (size_t)c_own * 4);
            a0 = s14.x + s2v.x; a1 = s14.y + s2v.y;
            a2 = s14.z + s2v.z; a3 = s14.w + s2v.w;
        }

        float b0 = a0, b1 = a1, b2 = a2, b3 = a3;
#pragma unroll
        for (int o = 16; o; o >>= 1) {
            b0 = fmaxf(b0, __shfl_xor_sync(0xffffffffu, b0, o));
            b1 = fmaxf(b1, __shfl_xor_sync(0xffffffffu, b1, o));
            b2 = fmaxf(b2, __shfl_xor_sync(0xffffffffu, b2, o));
            b3 = fmaxf(b3, __shfl_xor_sync(0xffffffffu, b3, o));
        }
        const float n0 = fmaxf(m0, b0), n1 = fmaxf(m1, b1);
        const float n2 = fmaxf(m2, b2), n3 = fmaxf(m3, b3);

        const float r0s = __expf(m0 - n0), r1s = __expf(m1 - n1);
        const float r2s = __expf(m2 - n2), r3s = __expf(m3 - n3);
        m0 = n0; m1 = n1; m2 = n2; m3 = n3;
        const float rA = hiHalf ? r1s : r0s;
        const float rB = hiHalf ? r3s : r2s;
        accA0 *= rA; accA1 *= rA; accB0 *= rB; accB1 *= rB;
        sum0 *= r0s; sum1 *= r1s; sum2 *= r2s; sum3 *= r3s;

        const float p0 = __expf(a0 - m0), p1 = __expf(a1 - m1);
        const float p2 = __expf(a2 - m2), p3 = __expf(a3 - m3);
        sum0 += p0; sum1 += p1; sum2 += p2; sum3 += p3;

        const int nb = min(32, e1 - blk);
#pragma unroll 4
        for (int j = 0; j < nb; j++) {
            const int   c  = __shfl_sync(0xffffffffu, c_own, j);
            const float w0 = __shfl_sync(0xffffffffu, p0, j);
            const float w1 = __shfl_sync(0xffffffffu, p1, j);
            const float w2 = __shfl_sync(0xffffffffu, p2, j);
            const float w3 = __shfl_sync(0xffffffffu, p3, j);
            const __half2* xr = (const __half2*)(g_xwh + (size_t)c * HD);
            const float2 fa = __half22float2(xr[lane]);
            const float2 fb = __half22float2(xr[32 + lane]);
            const float wA = hiHalf ? w1 : w0;
            const float wB = hiHalf ? w3 : w2;
            accA0 = fmaf(wA, fa.x, accA0);
            accA1 = fmaf(wA, fa.y, accA1);
            accB0 = fmaf(wB, fb.x, accB0);
            accB1 = fmaf(wB, fb.y, accB1);
        }
    }

#pragma unroll
    for (int o = 16; o; o >>= 1) {
        sum0 += __shfl_xor_sync(0xffffffffu, sum0, o);
        sum1 += __shfl_xor_sync(0xffffffffu, sum1, o);
        sum2 += __shfl_xor_sync(0xffffffffu, sum2, o);
        sum3 += __shfl_xor_sync(0xffffffffu, sum3, o);
    }
    const float i0 = 1.f / (sum0 + 1e-16f);
    const float i1 = 1.f / (sum1 + 1e-16f);
    const float i2 = 1.f / (sum2 + 1e-16f);
    const float i3 = 1.f / (sum3 + 1e-16f);
    const float iA = hiHalf ? i1 : i0;
    const float iB = hiHalf ? i3 : i2;

    float* o = out + (size_t)warp_id * HD;
    float2 cA = *(float2*)(o + 2 * lane);
    float2 cB = *(float2*)(o + 64 + 2 * lane);
    cA.x += accA0 * iA; cA.y += accA1 * iA;
    cB.x += accB0 * iB; cB.y += accB1 * iB;
    *(float2*)(o + 2 * lane)      = cA;
    *(float2*)(o + 64 + 2 * lane) = cB;
}

// ---------------- launch ---------------------------------------------------------
extern "C" void kernel_launch(void* const* d_in, const int* in_sizes, int n_in,
                              void* d_out, int out_size)
{
    const float* x   = (const float*)d_in[0];
    const int*   row = (const int*)d_in[1];
    const int*   col = (const int*)d_in[2];
    const float* a1w = (const float*)d_in[3];
    const float* a1b = (const float*)d_in[4];
    const float* a2w = (const float*)d_in[5];
    const float* a2b = (const float*)d_in[6];
    const float* llw = (const float*)d_in[7];
    const float* llb = (const float*)d_in[8];
    const float* lrw = (const float*)d_in[9];
    const float* lrb = (const float*)d_in[10];

    const int n = in_sizes[0] / K_DIM;
    const int e = in_sizes[1];
    float* outp = (float*)d_out;

    wprep_k<<<264, 256>>>(llw, llb, lrw, lrb, a1w, a1b, a2w, a2b);
    offsets_k<<<(n + 1 + 255) / 256, 256>>>(row, n, e);
    dim3 gg((n + 127) / 128, 2);
    gemm_mma_k<<<gg, 256>>>(x, outp, n);
    agg_k<<<(n * 32 + 255) / 256, 256>>>(col, outp, n);
}

// round 10
// speedup vs baseline: 2.1717x; 1.0132x over previous
#include <cuda_runtime.h>
#include <cuda_bf16.h>
#include <cuda_fp16.h>
#include <math.h>
#include <stdint.h>

#define K_DIM 256
#define HD 128
#define MAX_N 100000
#define MAX_E 1600000

// ---------------- scratch (static device arrays; no allocation) ----------------
__device__ __half g_xwh[(size_t)MAX_N * HD];      // x @ lin_l^T + b (fp16) [N,128]
__device__ float g_s1[(size_t)MAX_N * 4];         // a1 logits per node [N,4]
__device__ float g_s2[(size_t)MAX_N * 4];         // a2 logits per node [N,4]
__device__ int   g_off[MAX_N + 1];                // CSR offsets
__device__ __nv_bfloat16 g_bh[272 * 256];         // W_cat hi [264 used][256 k]
__device__ __nv_bfloat16 g_bl[272 * 256];         // W_cat lo
__device__ float g_bc[272];                       // bias cat (264 used)

// ---------------- PTX helpers ---------------------------------------------------
__device__ __forceinline__ uint32_t smem_u32(const void* p) {
    uint32_t a;
    asm("{ .reg .u64 t; cvta.to.shared.u64 t, %1; cvt.u32.u64 %0, t; }" : "=r"(a) : "l"(p));
    return a;
}
__device__ __forceinline__ void ldsm4(uint32_t* r, uint32_t addr) {
    asm volatile("ldmatrix.sync.aligned.m8n8.x4.shared.b16 {%0,%1,%2,%3}, [%4];"
                 : "=r"(r[0]), "=r"(r[1]), "=r"(r[2]), "=r"(r[3]) : "r"(addr));
}
__device__ __forceinline__ void ldsm2(uint32_t* r, uint32_t addr) {
    asm volatile("ldmatrix.sync.aligned.m8n8.x2.shared.b16 {%0,%1}, [%2];"
                 : "=r"(r[0]), "=r"(r[1]) : "r"(addr));
}
__device__ __forceinline__ void mma_bf16(float* c, const uint32_t* a, uint32_t b0, uint32_t b1) {
    asm volatile(
        "mma.sync.aligned.m16n8k16.row.col.f32.bf16.bf16.f32 "
        "{%0,%1,%2,%3}, {%4,%5,%6,%7}, {%8,%9}, {%0,%1,%2,%3};"
        : "+f"(c[0]), "+f"(c[1]), "+f"(c[2]), "+f"(c[3])
        : "r"(a[0]), "r"(a[1]), "r"(a[2]), "r"(a[3]), "r"(b0), "r"(b1));
}

// ---------------- weight prep: fp32 -> bf16 hi/lo, concat [lin_l|lin_r|a1|a2] ---
__global__ void wprep_k(const float* __restrict__ llw, const float* __restrict__ llb,
                        const float* __restrict__ lrw, const float* __restrict__ lrb,
                        const float* __restrict__ a1w, const float* __restrict__ a1b,
                        const float* __restrict__ a2w, const float* __restrict__ a2b)
{
    const int idx = blockIdx.x * blockDim.x + threadIdx.x;   // 0..67583
    const int n = idx >> 8, k = idx & 255;
    float v;
    if      (n < 128) v = llw[n * 256 + k];
    else if (n < 256) v = lrw[(n - 128) * 256 + k];
    else if (n < 260) v = a1w[(n - 256) * 256 + k];
    else              v = a2w[(n - 260) * 256 + k];
    const __nv_bfloat16 hi = __float2bfloat16(v);
    const __nv_bfloat16 lo = __float2bfloat16(v - __bfloat162float(hi));
    g_bh[idx] = hi;
    g_bl[idx] = lo;
    if (idx < 264) {
        float b;
        if      (idx < 128) b = llb[idx];
        else if (idx < 256) b = lrb[idx - 128];
        else if (idx < 260) b = a1b[idx - 256];
        else                b = a2b[idx - 260];
        g_bc[idx] = b;
    }
}

// ---------------- HMMA bf16-split GEMM + fused attention logits -----------------
#define LDS_STRIDE 40

__global__ void __launch_bounds__(256, 2)
gemm_mma_k(const float* __restrict__ A, float* __restrict__ outp, int M)
{
    __shared__ __align__(16) __nv_bfloat16 Ah[128 * LDS_STRIDE];
    __shared__ __align__(16) __nv_bfloat16 Al[128 * LDS_STRIDE];
    __shared__ __align__(16) __nv_bfloat16 Bh[128 * LDS_STRIDE];
    __shared__ __align__(16) __nv_bfloat16 Bl[128 * LDS_STRIDE];
    __shared__ __align__(16) __nv_bfloat16 Bxh[8 * LDS_STRIDE];
    __shared__ __align__(16) __nv_bfloat16 Bxl[8 * LDS_STRIDE];
    __shared__ float s_acc[128 * 9];

    const int tid = threadIdx.x;
    const int wid = tid >> 5;
    const int lane = tid & 31;
    const int bm = blockIdx.x * 128;
    const int by = blockIdx.y;
    const int warp_m = wid & 3;
    const int warp_n = wid >> 2;

    for (int i = tid; i < 128 * 9; i += 256) s_acc[i] = 0.f;

    float acc[2][8][4];
#pragma unroll
    for (int i = 0; i < 2; i++)
#pragma unroll
        for (int j = 0; j < 8; j++)
#pragma unroll
            for (int q = 0; q < 4; q++) acc[i][j][q] = 0.f;

    const int lrow = tid >> 1;
    const int lhalf = tid & 1;
    const bool avalid = (bm + lrow) < M;
    const float* ag = A + (size_t)(bm + lrow) * K_DIM + lhalf * 16;
    const __nv_bfloat16* bgh = g_bh + (size_t)(by * 128 + lrow) * 256 + lhalf * 16;
    const __nv_bfloat16* bgl = g_bl + (size_t)(by * 128 + lrow) * 256 + lhalf * 16;
    const __nv_bfloat16* bgxh = g_bh + (size_t)(256 + (tid >> 1)) * 256 + lhalf * 16;
    const __nv_bfloat16* bgxl = g_bl + (size_t)(256 + (tid >> 1)) * 256 + lhalf * 16;

    const uint32_t ah_s = smem_u32(Ah);
    const uint32_t al_s = smem_u32(Al);
    const uint32_t bh_s = smem_u32(Bh);
    const uint32_t bl_s = smem_u32(Bl);
    const uint32_t bxh_s = smem_u32(Bxh);
    const uint32_t bxl_s = smem_u32(Bxl);

    char* ah_p = (char*)Ah; char* al_p = (char*)Al;
    char* bh_p = (char*)Bh; char* bl_p = (char*)Bl;
    char* bxh_p = (char*)Bxh; char* bxl_p = (char*)Bxl;
    const uint32_t st_off = lrow * (LDS_STRIDE * 2) + lhalf * 32;

    for (int c = 0; c < 8; c++) {
        if (c) __syncthreads();

#pragma unroll
        for (int q = 0; q < 4; q++) {
            float4 f = avalid ? *(const float4*)(ag + c * 32 + q * 4) : make_float4(0, 0, 0, 0);
            __nv_bfloat162 h0 = __floats2bfloat162_rn(f.x, f.y);
            __nv_bfloat162 h1 = __floats2bfloat162_rn(f.z, f.w);
            float2 fh0 = __bfloat1622float2(h0), fh1 = __bfloat1622float2(h1);
            __nv_bfloat162 l0 = __floats2bfloat162_rn(f.x - fh0.x, f.y - fh0.y);
            __nv_bfloat162 l1 = __floats2bfloat162_rn(f.z - fh1.x, f.w - fh1.y);
            uint2 hv, lv;
            hv.x = *(uint32_t*)&h0; hv.y = *(uint32_t*)&h1;
            lv.x = *(uint32_t*)&l0; lv.y = *(uint32_t*)&l1;
            *(uint2*)(ah_p + st_off + q * 8) = hv;
            *(uint2*)(al_p + st_off + q * 8) = lv;
        }
        {
            const uint4* sh = (const uint4*)(bgh + c * 32);
            const uint4* sl = (const uint4*)(bgl + c * 32);
            *(uint4*)(bh_p + st_off)      = sh[0];
            *(uint4*)(bh_p + st_off + 16) = sh[1];
            *(uint4*)(bl_p + st_off)      = sl[0];
            *(uint4*)(bl_p + st_off + 16) = sl[1];
        }
        if (by == 0 && tid < 16) {
            const uint4* sh = (const uint4*)(bgxh + c * 32);
            const uint4* sl = (const uint4*)(bgxl + c * 32);
            *(uint4*)(bxh_p + st_off)      = sh[0];
            *(uint4*)(bxh_p + st_off + 16) = sh[1];
            *(uint4*)(bxl_p + st_off)      = sl[0];
            *(uint4*)(bxl_p + st_off + 16) = sl[1];
        }
        __syncthreads();

        float cx[2][4] = {{0.f, 0.f, 0.f, 0.f}, {0.f, 0.f, 0.f, 0.f}};

#pragma unroll
        for (int ks = 0; ks < 2; ks++) {
            const uint32_t kb = ks * 32 + (lane >> 4) * 16;
            uint32_t a_h[2][4], a_l[2][4];
#pragma unroll
            for (int mt = 0; mt < 2; mt++) {
                const uint32_t ro = (warp_m * 32 + mt * 16 + (lane & 15)) * (LDS_STRIDE * 2) + kb;
                ldsm4(a_h[mt], ah_s + ro);
                ldsm4(a_l[mt], al_s + ro);
            }
#pragma unroll
            for (int nt = 0; nt < 4; nt++) {
                const uint32_t ro = (warp_n * 64 + nt * 16 + (lane & 15)) * (LDS_STRIDE * 2) + kb;
                uint32_t b_h[4], b_l[4];
                ldsm4(b_h, bh_s + ro);
                ldsm4(b_l, bl_s + ro);
#pragma unroll
                for (int mt = 0; mt < 2; mt++) {
                    mma_bf16(acc[mt][nt * 2],     a_h[mt], b_h[0], b_h[2]);
                    mma_bf16(acc[mt][nt * 2 + 1], a_h[mt], b_h[1], b_h[3]);
                    mma_bf16(acc[mt][nt * 2],     a_h[mt], b_l[0], b_l[2]);
                    mma_bf16(acc[mt][nt * 2 + 1], a_h[mt], b_l[1], b_l[3]);
                    mma_bf16(acc[mt][nt * 2],     a_l[mt], b_h[0], b_h[2]);
                    mma_bf16(acc[mt][nt * 2 + 1], a_l[mt], b_h[1], b_h[3]);
                }
            }
            if (by == 0 && warp_n == 0) {
                const int la = lane & 15;
                const uint32_t rox = (la & 7) * (LDS_STRIDE * 2) + ((la >> 3) & 1) * 16 + ks * 32;
                uint32_t bx_h[2], bx_l[2];
                ldsm2(bx_h, bxh_s + rox);
                ldsm2(bx_l, bxl_s + rox);
#pragma unroll
                for (int mt = 0; mt < 2; mt++) {
                    mma_bf16(cx[mt], a_h[mt], bx_h[0], bx_h[1]);
                    mma_bf16(cx[mt], a_h[mt], bx_l[0], bx_l[1]);
                    mma_bf16(cx[mt], a_l[mt], bx_h[0], bx_h[1]);
                }
            }
        }
        if (by == 0 && warp_n == 0) {
#pragma unroll
            for (int mt = 0; mt < 2; mt++) {
                const int r = warp_m * 32 + mt * 16 + (lane >> 2);
                const int cc = (lane & 3) * 2;
                s_acc[r * 9 + cc]           += cx[mt][0];
                s_acc[r * 9 + cc + 1]       += cx[mt][1];
                s_acc[(r + 8) * 9 + cc]     += cx[mt][2];
                s_acc[(r + 8) * 9 + cc + 1] += cx[mt][3];
            }
        }
    }

    if (by == 0) {
#pragma unroll
        for (int mt = 0; mt < 2; mt++) {
            const int r0 = bm + warp_m * 32 + mt * 16 + (lane >> 2);
#pragma unroll
            for (int nt2 = 0; nt2 < 8; nt2++) {
                const int cc = warp_n * 64 + nt2 * 8 + (lane & 3) * 2;
                const float b0 = g_bc[cc], b1 = g_bc[cc + 1];
                if (r0 < M)
                    *(__half2*)(g_xwh + (size_t)r0 * HD + cc) =
                        __floats2half2_rn(acc[mt][nt2][0] + b0, acc[mt][nt2][1] + b1);
                if (r0 + 8 < M)
                    *(__half2*)(g_xwh + (size_t)(r0 + 8) * HD + cc) =
                        __floats2half2_rn(acc[mt][nt2][2] + b0, acc[mt][nt2][3] + b1);
            }
        }
        __syncthreads();
#pragma unroll
        for (int it = 0; it < 4; it++) {
            const int idx = tid + it * 256;
            const int r = idx >> 3, cc = idx & 7;
            const int gr = bm + r;
            if (gr < M) {
                const float v = s_acc[r * 9 + cc] + g_bc[256 + cc];
                if (cc < 4) g_s1[(size_t)gr * 4 + cc] = v;
                else        g_s2[(size_t)gr * 4 + cc - 4] = v;
            }
        }
    } else {
        const float* bias = g_bc + 128;
#pragma unroll
        for (int mt = 0; mt < 2; mt++) {
            const int r0 = bm + warp_m * 32 + mt * 16 + (lane >> 2);
#pragma unroll
            for (int nt2 = 0; nt2 < 8; nt2++) {
                const int cc = warp_n * 64 + nt2 * 8 + (lane & 3) * 2;
                const float b0 = bias[cc], b1 = bias[cc + 1];
                if (r0 < M)
                    *(float2*)(outp + (size_t)r0 * HD + cc) =
                        make_float2(acc[mt][nt2][0] + b0, acc[mt][nt2][1] + b1);
                if (r0 + 8 < M)
                    *(float2*)(outp + (size_t)(r0 + 8) * HD + cc) =
                        make_float2(acc[mt][nt2][2] + b0, acc[mt][nt2][3] + b1);
            }
        }
    }
}

// ---------------- CSR offsets (windowed binary search + fallback) ---------------
__global__ void offsets_k(const int* __restrict__ row, int n, int e)
{
    const int i = blockIdx.x * blockDim.x + threadIdx.x;
    if (i > n) return;
    // expected position for uniform row distribution
    const int g = (int)((long long)i * e / n);
    int lo = g - 4096; if (lo < 0) lo = 0;
    int hi = g + 4096; if (hi > e) hi = e;
    // validate bracket; fallback to full range if the window misses
    const bool ok_lo = (lo == 0) || (row[lo - 1] < i);
    const bool ok_hi = (hi == e) || (row[hi - 1] >= i);
    if (!(ok_lo && ok_hi)) { lo = 0; hi = e; }
    while (lo < hi) {
        const int mid = (lo + hi) >> 1;
        if (row[mid] < i) lo = mid + 1; else hi = mid;
    }
    g_off[i] = lo;
}

// ---------------- segment softmax + aggregation (smem-staged, 1 LDG/edge) -------
__global__ void __launch_bounds__(256)
agg_k(const int* __restrict__ col, float* __restrict__ out, int n)
{
    __shared__ float sw[8][32][4];   // [warp][edge][head] softmax numerators
    __shared__ int   sc[8][32];      // [warp][edge] col index

    const int wl = threadIdx.x >> 5;                 // warp within block
    const int warp_id = (blockIdx.x * blockDim.x + threadIdx.x) >> 5;
    const int lane = threadIdx.x & 31;
    if (warp_id >= n) return;

    const int e0 = g_off[warp_id];
    const int e1 = g_off[warp_id + 1];
    if (e0 >= e1) return;   // isolated node: out already holds lin_r part

    const float4 s14 = *(const float4*)(g_s1 + (size_t)warp_id * 4);
    const int head = lane >> 3;                      // this lane's head (features 4l..4l+3)

    float m0 = -INFINITY, m1 = -INFINITY, m2 = -INFINITY, m3 = -INFINITY;
    float sum0 = 0.f, sum1 = 0.f, sum2 = 0.f, sum3 = 0.f;
    float acc0 = 0.f, acc1 = 0.f, acc2 = 0.f, acc3 = 0.f;

    for (int blk = e0; blk < e1; blk += 32) {
        const int idx = blk + lane;
        const bool v = idx < e1;
        const int c_own = v ? col[idx] : 0;

        float a0 = -INFINITY, a1 = -INFINITY, a2 = -INFINITY, a3 = -INFINITY;
        if (v) {
            const float4 s2v = *(const float4*)(g_s2 + (size_t)c_own * 4);
            a0 = s14.x + s2v.x; a1 = s14.y + s2v.y;
            a2 = s14.z + s2v.z; a3 = s14.w + s2v.w;
        }

        // per-head block max
        float b0 = a0, b1 = a1, b2 = a2, b3 = a3;
#pragma unroll
        for (int o = 16; o; o >>= 1) {
            b0 = fmaxf(b0, __shfl_xor_sync(0xffffffffu, b0, o));
            b1 = fmaxf(b1, __shfl_xor_sync(0xffffffffu, b1, o));
            b2 = fmaxf(b2, __shfl_xor_sync(0xffffffffu, b2, o));
            b3 = fmaxf(b3, __shfl_xor_sync(0xffffffffu, b3, o));
        }
        const float n0 = fmaxf(m0, b0), n1 = fmaxf(m1, b1);
        const float n2 = fmaxf(m2, b2), n3 = fmaxf(m3, b3);

        const float r0 = __expf(m0 - n0), r1 = __expf(m1 - n1);
        const float r2 = __expf(m2 - n2), r3 = __expf(m3 - n3);
        m0 = n0; m1 = n1; m2 = n2; m3 = n3;
        sum0 *= r0; sum1 *= r1; sum2 *= r2; sum3 *= r3;
        const float rsel = (head == 0) ? r0 : (head == 1) ? r1 : (head == 2) ? r2 : r3;
        acc0 *= rsel; acc1 *= rsel; acc2 *= rsel; acc3 *= rsel;

        const float p0 = __expf(a0 - m0), p1 = __expf(a1 - m1);
        const float p2 = __expf(a2 - m2), p3 = __expf(a3 - m3);
        sum0 += p0; sum1 += p1; sum2 += p2; sum3 += p3;

        // stage this block's weights + cols in warp-private smem
        sc[wl][lane] = c_own;
        *(float4*)&sw[wl][lane][0] = make_float4(p0, p1, p2, p3);
        __syncwarp();

        const int nb = min(32, e1 - blk);
#pragma unroll 4
        for (int j = 0; j < nb; j++) {
            const int   c = sc[wl][j];
            const float w = sw[wl][j][head];
            const uint2 u = *((const uint2*)(g_xwh + (size_t)c * HD) + lane);
            const float2 f0 = __half22float2(*(const __half2*)&u.x);
            const float2 f1 = __half22float2(*(const __half2*)&u.y);
            acc0 = fmaf(w, f0.x, acc0);
            acc1 = fmaf(w, f0.y, acc1);
            acc2 = fmaf(w, f1.x, acc2);
            acc3 = fmaf(w, f1.y, acc3);
        }
        __syncwarp();
    }

#pragma unroll
    for (int o = 16; o; o >>= 1) {
        sum0 += __shfl_xor_sync(0xffffffffu, sum0, o);
        sum1 += __shfl_xor_sync(0xffffffffu, sum1, o);
        sum2 += __shfl_xor_sync(0xffffffffu, sum2, o);
        sum3 += __shfl_xor_sync(0xffffffffu, sum3, o);
    }
    const float ssel = (head == 0) ? sum0 : (head == 1) ? sum1 : (head == 2) ? sum2 : sum3;
    const float inv = 1.f / (ssel + 1e-16f);

    float* o = out + (size_t)warp_id * HD + lane * 4;
    float4 cv = *(float4*)o;
    cv.x += acc0 * inv; cv.y += acc1 * inv;
    cv.z += acc2 * inv; cv.w += acc3 * inv;
    *(float4*)o = cv;
}

// ---------------- launch ---------------------------------------------------------
extern "C" void kernel_launch(void* const* d_in, const int* in_sizes, int n_in,
                              void* d_out, int out_size)
{
    const float* x   = (const float*)d_in[0];
    const int*   row = (const int*)d_in[1];
    const int*   col = (const int*)d_in[2];
    const float* a1w = (const float*)d_in[3];
    const float* a1b = (const float*)d_in[4];
    const float* a2w = (const float*)d_in[5];
    const float* a2b = (const float*)d_in[6];
    const float* llw = (const float*)d_in[7];
    const float* llb = (const float*)d_in[8];
    const float* lrw = (const float*)d_in[9];
    const float* lrb = (const float*)d_in[10];

    const int n = in_sizes[0] / K_DIM;
    const int e = in_sizes[1];
    float* outp = (float*)d_out;

    wprep_k<<<264, 256>>>(llw, llb, lrw, lrb, a1w, a1b, a2w, a2b);
    offsets_k<<<(n + 1 + 255) / 256, 256>>>(row, n, e);
    dim3 gg((n + 127) / 128, 2);
    gemm_mma_k<<<gg, 256>>>(x, outp, n);
    agg_k<<<(n * 32 + 255) / 256, 256>>>(col, outp, n);
}